// round 1
// baseline (speedup 1.0000x reference)
#include <cuda_runtime.h>
#include <mma.h>
#include <math.h>
#include <stdint.h>

using namespace nvcuda;

// Problem constants
constexpr int HD   = 1024;   // hidden
constexpr int ID   = 512;    // moe intermediate
constexpr int NEXP = 16;     // routed experts
constexpr int TOPK = 4;
constexpr int NT   = 2048;   // tokens (B*S)
constexpr int NE   = 17;     // routed experts + shared expert as pseudo-expert 16

// ---------------- device scratch (no allocations allowed) ----------------
__device__ int   g_cnt[NE];
__device__ int   g_tok[NE * NT];
__device__ float g_rw [NE * NT];
__device__ float g_act[(size_t)NE * NT * ID];   // ~71 MB gathered activations

// ---------------- init: zero out, reset counters, install shared expert ----------------
__global__ void k_init(float* __restrict__ out) {
    int idx = blockIdx.x * blockDim.x + threadIdx.x;   // 2048*256 = 524288 threads
    // zero output: 2,097,152 floats = 524,288 float4
    reinterpret_cast<float4*>(out)[idx] = make_float4(0.f, 0.f, 0.f, 0.f);
    if (idx < NE) g_cnt[idx] = (idx == NEXP) ? NT : 0;
    if (idx < NT) {                     // shared expert token list: identity, weight 1
        g_tok[NEXP * NT + idx] = idx;
        g_rw [NEXP * NT + idx] = 1.0f;
    }
}

// ---------------- router: fp32 logits, sigmoid, top-4, scatter ----------------
__global__ void k_router(const float* __restrict__ x, const float* __restrict__ rw) {
    const int t    = blockIdx.x;
    const int wid  = threadIdx.x >> 5;
    const int lane = threadIdx.x & 31;
    __shared__ float sl[NEXP];

    const float* xr = x + (size_t)t * HD;
    float acc = 0.f;
    for (int h = lane; h < HD; h += 32)
        acc += xr[h] * rw[h * NEXP + wid];
    #pragma unroll
    for (int o = 16; o > 0; o >>= 1)
        acc += __shfl_down_sync(0xffffffffu, acc, o);
    if (lane == 0) sl[wid] = acc;
    __syncthreads();

    if (threadIdx.x == 0) {
        float v[NEXP]; bool used[NEXP];
        #pragma unroll
        for (int e = 0; e < NEXP; e++) {
            v[e] = 1.f / (1.f + expf(-sl[e]));
            used[e] = false;
        }
        #pragma unroll
        for (int k = 0; k < TOPK; k++) {
            int be = -1; float bv = -1.f;
            #pragma unroll
            for (int e = 0; e < NEXP; e++)
                if (!used[e] && v[e] > bv) { bv = v[e]; be = e; }   // strict > : lowest index on ties
            used[be] = true;
            int j = atomicAdd(&g_cnt[be], 1);
            g_tok[be * NT + j] = t;
            g_rw [be * NT + j] = bv;
        }
    }
}

// ---------------- gate/up GEMM + silu epilogue (tf32 wmma) ----------------
// Tile: BM=64 rows (gathered tokens), BN=64 of I, K=HD in BK=16 steps.
// 8 warps as 2(m) x 4(n); each warp: 32x16 of G and 32x16 of U.
__global__ void __launch_bounds__(256)
k_gateup(const float* __restrict__ x,
         const float* __restrict__ gate_w, const float* __restrict__ up_w,
         const float* __restrict__ sgate,  const float* __restrict__ sup) {
    const int e    = blockIdx.z;
    const int c    = g_cnt[e];
    const int row0 = blockIdx.x * 64;
    if (row0 >= c) return;
    const int n0   = blockIdx.y * 64;

    const float* Wg = (e == NEXP) ? sgate : gate_w + (size_t)e * HD * ID;
    const float* Wu = (e == NEXP) ? sup   : up_w   + (size_t)e * HD * ID;

    __shared__ union {
        struct { float Xs[64 * 20]; float Gw[16 * 68]; float Uw[16 * 68]; } s;
        float Cs[2 * 64 * 68];          // epilogue G|U staging (aliases load buffers)
    } sm;
    __shared__ int   toks[64];
    __shared__ float rws [64];

    const int tid = threadIdx.x;
    if (tid < 64) {
        int row = row0 + tid;
        if (row < c) { toks[tid] = g_tok[e * NT + row]; rws[tid] = g_rw[e * NT + row]; }
        else         { toks[tid] = -1;                  rws[tid] = 0.f; }
    }
    __syncthreads();

    const int wid = tid >> 5;
    const int wm  = wid >> 2;         // 0..1
    const int wn  = wid & 3;          // 0..3

    wmma::fragment<wmma::accumulator, 16, 16, 8, float> accG[2], accU[2];
    wmma::fill_fragment(accG[0], 0.f); wmma::fill_fragment(accG[1], 0.f);
    wmma::fill_fragment(accU[0], 0.f); wmma::fill_fragment(accU[1], 0.f);

    const int lr  = tid >> 2, lc4 = tid & 3;    // X loader: 64 rows x 4 float4
    const int wr  = tid >> 4, wc4 = tid & 15;   // W loader: 16 rows x 16 float4
    const int tk  = (tid < 256) ? 0 : 0;        // (silence)
    (void)tk;

    for (int kk = 0; kk < HD; kk += 16) {
        float4 xv = make_float4(0.f, 0.f, 0.f, 0.f);
        int tok = toks[lr];
        if (tok >= 0)
            xv = *reinterpret_cast<const float4*>(x + (size_t)tok * HD + kk + lc4 * 4);
        *reinterpret_cast<float4*>(sm.s.Xs + lr * 20 + lc4 * 4) = xv;

        *reinterpret_cast<float4*>(sm.s.Gw + wr * 68 + wc4 * 4) =
            *reinterpret_cast<const float4*>(Wg + (size_t)(kk + wr) * ID + n0 + wc4 * 4);
        *reinterpret_cast<float4*>(sm.s.Uw + wr * 68 + wc4 * 4) =
            *reinterpret_cast<const float4*>(Wu + (size_t)(kk + wr) * ID + n0 + wc4 * 4);
        __syncthreads();

        #pragma unroll
        for (int ks = 0; ks < 16; ks += 8) {
            wmma::fragment<wmma::matrix_a, 16, 16, 8, wmma::precision::tf32, wmma::row_major> a0, a1;
            wmma::fragment<wmma::matrix_b, 16, 16, 8, wmma::precision::tf32, wmma::row_major> bg, bu;
            wmma::load_matrix_sync(a0, sm.s.Xs + (wm * 32)      * 20 + ks, 20);
            wmma::load_matrix_sync(a1, sm.s.Xs + (wm * 32 + 16) * 20 + ks, 20);
            wmma::load_matrix_sync(bg, sm.s.Gw + ks * 68 + wn * 16, 68);
            wmma::load_matrix_sync(bu, sm.s.Uw + ks * 68 + wn * 16, 68);
            #pragma unroll
            for (int i = 0; i < a0.num_elements; i++) {
                a0.x[i] = wmma::__float_to_tf32(a0.x[i]);
                a1.x[i] = wmma::__float_to_tf32(a1.x[i]);
            }
            #pragma unroll
            for (int i = 0; i < bg.num_elements; i++) {
                bg.x[i] = wmma::__float_to_tf32(bg.x[i]);
                bu.x[i] = wmma::__float_to_tf32(bu.x[i]);
            }
            wmma::mma_sync(accG[0], a0, bg, accG[0]);
            wmma::mma_sync(accG[1], a1, bg, accG[1]);
            wmma::mma_sync(accU[0], a0, bu, accU[0]);
            wmma::mma_sync(accU[1], a1, bu, accU[1]);
        }
        __syncthreads();
    }

    // epilogue: silu(r*g) * (r*u)
    float* Gs = sm.Cs;
    float* Us = sm.Cs + 64 * 68;
    wmma::store_matrix_sync(Gs + (wm * 32)      * 68 + wn * 16, accG[0], 68, wmma::mem_row_major);
    wmma::store_matrix_sync(Gs + (wm * 32 + 16) * 68 + wn * 16, accG[1], 68, wmma::mem_row_major);
    wmma::store_matrix_sync(Us + (wm * 32)      * 68 + wn * 16, accU[0], 68, wmma::mem_row_major);
    wmma::store_matrix_sync(Us + (wm * 32 + 16) * 68 + wn * 16, accU[1], 68, wmma::mem_row_major);
    __syncthreads();

    for (int idx = tid; idx < 64 * 64; idx += 256) {
        int r  = idx >> 6;
        int cc = idx & 63;
        float rr = rws[r];
        float g  = rr * Gs[r * 68 + cc];
        float u  = rr * Us[r * 68 + cc];
        float a  = (g / (1.f + expf(-g))) * u;       // silu(g)*u  (exact 0 for padded rows)
        g_act[((size_t)e * NT + row0 + r) * ID + n0 + cc] = a;
    }
}

// ---------------- down GEMM + scatter-add (tf32 wmma) ----------------
// Tile: BM=64 act rows, BN=64 of H, K=ID=512 in BK=16 steps.
__global__ void __launch_bounds__(256)
k_down(const float* __restrict__ down_w, const float* __restrict__ sdown,
       float* __restrict__ out) {
    const int e    = blockIdx.z;
    const int c    = g_cnt[e];
    const int row0 = blockIdx.x * 64;
    if (row0 >= c) return;
    const int n0   = blockIdx.y * 64;

    const float* Wd = (e == NEXP) ? sdown : down_w + (size_t)e * ID * HD;

    __shared__ union {
        struct { float As[64 * 20]; float Bw[16 * 68]; } s;
        float Cs[64 * 68];
    } sm;
    __shared__ int toks[64];

    const int tid = threadIdx.x;
    if (tid < 64) {
        int row = row0 + tid;
        toks[tid] = (row < c) ? g_tok[e * NT + row] : 0;
    }
    __syncthreads();

    const int wid = tid >> 5;
    const int wm  = wid >> 2;
    const int wn  = wid & 3;

    wmma::fragment<wmma::accumulator, 16, 16, 8, float> acc[2];
    wmma::fill_fragment(acc[0], 0.f); wmma::fill_fragment(acc[1], 0.f);

    const int lr = tid >> 2, lc4 = tid & 3;
    const int wr = tid >> 4, wc4 = tid & 15;

    const float* Abase = g_act + ((size_t)e * NT + row0) * ID;

    for (int kk = 0; kk < ID; kk += 16) {
        // padded rows (>= c) within an active tile contain exact zeros from k_gateup
        *reinterpret_cast<float4*>(sm.s.As + lr * 20 + lc4 * 4) =
            *reinterpret_cast<const float4*>(Abase + (size_t)lr * ID + kk + lc4 * 4);
        *reinterpret_cast<float4*>(sm.s.Bw + wr * 68 + wc4 * 4) =
            *reinterpret_cast<const float4*>(Wd + (size_t)(kk + wr) * HD + n0 + wc4 * 4);
        __syncthreads();

        #pragma unroll
        for (int ks = 0; ks < 16; ks += 8) {
            wmma::fragment<wmma::matrix_a, 16, 16, 8, wmma::precision::tf32, wmma::row_major> a0, a1;
            wmma::fragment<wmma::matrix_b, 16, 16, 8, wmma::precision::tf32, wmma::row_major> b;
            wmma::load_matrix_sync(a0, sm.s.As + (wm * 32)      * 20 + ks, 20);
            wmma::load_matrix_sync(a1, sm.s.As + (wm * 32 + 16) * 20 + ks, 20);
            wmma::load_matrix_sync(b,  sm.s.Bw + ks * 68 + wn * 16, 68);
            #pragma unroll
            for (int i = 0; i < a0.num_elements; i++) {
                a0.x[i] = wmma::__float_to_tf32(a0.x[i]);
                a1.x[i] = wmma::__float_to_tf32(a1.x[i]);
            }
            #pragma unroll
            for (int i = 0; i < b.num_elements; i++)
                b.x[i] = wmma::__float_to_tf32(b.x[i]);
            wmma::mma_sync(acc[0], a0, b, acc[0]);
            wmma::mma_sync(acc[1], a1, b, acc[1]);
        }
        __syncthreads();
    }

    wmma::store_matrix_sync(sm.Cs + (wm * 32)      * 68 + wn * 16, acc[0], 68, wmma::mem_row_major);
    wmma::store_matrix_sync(sm.Cs + (wm * 32 + 16) * 68 + wn * 16, acc[1], 68, wmma::mem_row_major);
    __syncthreads();

    for (int idx = tid; idx < 64 * 64; idx += 256) {
        int r  = idx >> 6;
        int cc = idx & 63;
        if (row0 + r < c)
            atomicAdd(&out[(size_t)toks[r] * HD + n0 + cc], sm.Cs[r * 68 + cc]);
    }
}

// ---------------- launch ----------------
extern "C" void kernel_launch(void* const* d_in, const int* in_sizes, int n_in,
                              void* d_out, int out_size) {
    (void)in_sizes; (void)n_in; (void)out_size;
    const float* x     = (const float*)d_in[0];
    const float* rw    = (const float*)d_in[1];
    const float* gate  = (const float*)d_in[2];
    const float* up    = (const float*)d_in[3];
    const float* down  = (const float*)d_in[4];
    const float* sgate = (const float*)d_in[5];
    const float* sup   = (const float*)d_in[6];
    const float* sdown = (const float*)d_in[7];
    float* out = (float*)d_out;

    k_init  <<<2048, 256>>>(out);
    k_router<<<NT, 512>>>(x, rw);
    k_gateup<<<dim3(NT / 64, ID / 64, NE), 256>>>(x, gate, up, sgate, sup);
    k_down  <<<dim3(NT / 64, HD / 64, NE), 256>>>(down, sdown, out);
}

// round 4
// speedup vs baseline: 2.0984x; 2.0984x over previous
#include <cuda_runtime.h>
#include <math.h>
#include <stdint.h>

// ---------------- problem constants ----------------
constexpr int HD   = 1024;
constexpr int ID   = 512;
constexpr int NEXP = 16;
constexpr int TOPK = 4;
constexpr int NT   = 2048;
constexpr int NE   = 17;          // 16 routed + shared pseudo-expert

// ---------------- device scratch ----------------
__device__ int   g_cnt[NE];
__device__ int   g_tok[NE * NT];
__device__ float g_rw [NE * NT];
__device__ int   g_pos[NT * TOPK];
__device__ float g_act[(size_t)NE * NT * ID];   // gathered SwiGLU activations
__device__ float g_dn [(size_t)NE * NT * HD];   // per-(expert,slot) down outputs

// ---------------- helpers ----------------
__device__ __forceinline__ uint32_t smem_u32(const void* p) {
    uint32_t a;
    asm("{ .reg .u64 t; cvta.to.shared.u64 t, %1; cvt.u32.u64 %0, t; }" : "=r"(a) : "l"(p));
    return a;
}
__device__ __forceinline__ uint32_t f2tf32(float v) {       // round-to-nearest tf32
    uint32_t o;
    asm("cvt.rna.tf32.f32 %0, %1;" : "=r"(o) : "f"(v));
    return o;
}
__device__ __forceinline__ void cp16(uint32_t dst, const void* src) {
    asm volatile("cp.async.cg.shared.global [%0], [%1], 16;" :: "r"(dst), "l"(src));
}
#define CP_COMMIT() asm volatile("cp.async.commit_group;" ::: "memory")
#define CP_WAIT(n)  asm volatile("cp.async.wait_group %0;" :: "n"(n) : "memory")

// m16n8k8 tf32 mma, fragments per PTX ISA:
//  A: a0=(g,tg) a1=(g+8,tg) a2=(g,tg+4) a3=(g+8,tg+4)   [g=lane>>2, tg=lane&3]
//  B: b0=(k=tg,n=g) b1=(k=tg+4,n=g)
//  C: c0=(g,2tg) c1=(g,2tg+1) c2=(g+8,2tg) c3=(g+8,2tg+1)
__device__ __forceinline__ void mma8(float* c, const uint32_t* a, const uint32_t* b) {
    asm volatile(
        "mma.sync.aligned.m16n8k8.row.col.f32.tf32.tf32.f32 "
        "{%0,%1,%2,%3}, {%4,%5,%6,%7}, {%8,%9}, {%0,%1,%2,%3};"
        : "+f"(c[0]), "+f"(c[1]), "+f"(c[2]), "+f"(c[3])
        : "r"(a[0]), "r"(a[1]), "r"(a[2]), "r"(a[3]), "r"(b[0]), "r"(b[1]));
}
__device__ __forceinline__ float silu(float g) { return g / (1.f + expf(-g)); }

// ---------------- init ----------------
__global__ void k_init() {
    int idx = blockIdx.x * blockDim.x + threadIdx.x;
    if (idx < NE) g_cnt[idx] = (idx == NEXP) ? NT : 0;
    if (idx < NT) { g_tok[NEXP * NT + idx] = idx; g_rw[NEXP * NT + idx] = 1.0f; }
}

// ---------------- router ----------------
__global__ void k_router(const float* __restrict__ x, const float* __restrict__ rw) {
    const int t    = blockIdx.x;
    const int wid  = threadIdx.x >> 5;
    const int lane = threadIdx.x & 31;
    __shared__ float sl[NEXP];

    const float* xr = x + (size_t)t * HD;
    float acc = 0.f;
    for (int h = lane; h < HD; h += 32)
        acc += xr[h] * rw[h * NEXP + wid];
    #pragma unroll
    for (int o = 16; o > 0; o >>= 1)
        acc += __shfl_down_sync(0xffffffffu, acc, o);
    if (lane == 0) sl[wid] = acc;
    __syncthreads();

    if (threadIdx.x == 0) {
        float v[NEXP]; bool used[NEXP];
        #pragma unroll
        for (int e = 0; e < NEXP; e++) { v[e] = 1.f / (1.f + expf(-sl[e])); used[e] = false; }
        #pragma unroll
        for (int k = 0; k < TOPK; k++) {
            int be = -1; float bv = -1.f;
            #pragma unroll
            for (int e = 0; e < NEXP; e++)
                if (!used[e] && v[e] > bv) { bv = v[e]; be = e; }
            used[be] = true;
            int j = atomicAdd(&g_cnt[be], 1);
            g_tok[be * NT + j] = t;
            g_rw [be * NT + j] = bv;
            g_pos[t * TOPK + k] = be * NT + j;
        }
    }
}

// =======================================================================
// gate/up GEMM: BM=128 tokens, BN=64 of I, computing BOTH G and U.
// 8 warps = 4(m) x 2(n); warp tile 32 rows x 32 cols for G and U.
// K=HD=1024, BK=32, cp.async double-buffered.
// smem floats: toks[128]i rws[128] | A[2][128*36] Bg[2][32*72] Bu[2][32*72]
// =======================================================================
constexpr int GU_A0 = 256, GU_A1 = GU_A0 + 128 * 36;
constexpr int GU_G0 = GU_A1 + 128 * 36, GU_G1 = GU_G0 + 32 * 72;
constexpr int GU_U0 = GU_G1 + 32 * 72,  GU_U1 = GU_U0 + 32 * 72;
constexpr int GU_SMEM = (GU_U1 + 32 * 72) * 4;   // 74752 B

__global__ void __launch_bounds__(256)
k_gateup(const float* __restrict__ x,
         const float* __restrict__ gate_w, const float* __restrict__ up_w,
         const float* __restrict__ sgate,  const float* __restrict__ sup) {
    const int e    = blockIdx.z;
    const int c    = g_cnt[e];
    const int row0 = blockIdx.x * 128;
    if (row0 >= c) return;
    const int n0   = blockIdx.y * 64;

    extern __shared__ float sm[];
    int*   toks = (int*)sm;
    float* rws  = sm + 128;
    const uint32_t sb = smem_u32(sm);
    const int tid = threadIdx.x;

    const float* Wg = (e == NEXP) ? sgate : gate_w + (size_t)e * HD * ID;
    const float* Wu = (e == NEXP) ? sup   : up_w   + (size_t)e * HD * ID;

    if (tid < 128) {
        int r = row0 + tid;
        if (r < c) { toks[tid] = g_tok[e * NT + r]; rws[tid] = g_rw[e * NT + r]; }
        else       { toks[tid] = 0;                 rws[tid] = 0.f; }   // token 0, weight 0
    }
    __syncthreads();

    auto load_stage = [&](int buf, int kk) {
        const int a_off = buf ? GU_A1 : GU_A0;
        const int g_off = buf ? GU_G1 : GU_G0;
        const int u_off = buf ? GU_U1 : GU_U0;
        #pragma unroll
        for (int i = 0; i < 4; i++) {              // A: 128 rows x 32 f = 1024 chunks
            int lin = tid + i * 256;
            int r = lin >> 3, ch = lin & 7;
            cp16(sb + (a_off + r * 36 + ch * 4) * 4,
                 x + (size_t)toks[r] * HD + kk + ch * 4);
        }
        #pragma unroll
        for (int i = 0; i < 2; i++) {              // Bg: 32 k x 64 f = 512 chunks
            int lin = tid + i * 256;
            int k = lin >> 4, ch = lin & 15;
            cp16(sb + (g_off + k * 72 + ch * 4) * 4,
                 Wg + (size_t)(kk + k) * ID + n0 + ch * 4);
        }
        #pragma unroll
        for (int i = 0; i < 2; i++) {              // Bu
            int lin = tid + i * 256;
            int k = lin >> 4, ch = lin & 15;
            cp16(sb + (u_off + k * 72 + ch * 4) * 4,
                 Wu + (size_t)(kk + k) * ID + n0 + ch * 4);
        }
    };

    const int wid = tid >> 5, lane = tid & 31;
    const int gid = lane >> 2, tg = lane & 3;
    const int wm = wid & 3, wn = wid >> 2;          // 4m x 2n

    float accG[2][4][4] = {}, accU[2][4][4] = {};

    load_stage(0, 0);
    CP_COMMIT();

    const int S = HD / 32;                           // 32 stages
    for (int s = 0; s < S; s++) {
        if (s + 1 < S) { load_stage((s + 1) & 1, (s + 1) * 32); CP_COMMIT(); CP_WAIT(1); }
        else           { CP_WAIT(0); }
        __syncthreads();

        const float* As = sm + ((s & 1) ? GU_A1 : GU_A0);
        const float* Gs = sm + ((s & 1) ? GU_G1 : GU_G0);
        const float* Us = sm + ((s & 1) ? GU_U1 : GU_U0);

        #pragma unroll
        for (int kq = 0; kq < 4; kq++) {
            uint32_t a[2][4], bg[4][2], bu[4][2];
            #pragma unroll
            for (int mf = 0; mf < 2; mf++) {
                const float* ap = As + (wm * 32 + mf * 16 + gid) * 36 + kq * 8 + tg;
                a[mf][0] = f2tf32(ap[0]);
                a[mf][1] = f2tf32(ap[8 * 36]);
                a[mf][2] = f2tf32(ap[4]);
                a[mf][3] = f2tf32(ap[8 * 36 + 4]);
            }
            #pragma unroll
            for (int nf = 0; nf < 4; nf++) {
                const float* gp = Gs + (kq * 8 + tg) * 72 + wn * 32 + nf * 8 + gid;
                bg[nf][0] = f2tf32(gp[0]); bg[nf][1] = f2tf32(gp[4 * 72]);
                const float* up = Us + (kq * 8 + tg) * 72 + wn * 32 + nf * 8 + gid;
                bu[nf][0] = f2tf32(up[0]); bu[nf][1] = f2tf32(up[4 * 72]);
            }
            #pragma unroll
            for (int mf = 0; mf < 2; mf++)
                #pragma unroll
                for (int nf = 0; nf < 4; nf++) {
                    mma8(accG[mf][nf], a[mf], bg[nf]);
                    mma8(accU[mf][nf], a[mf], bu[nf]);
                }
        }
        __syncthreads();
    }

    // register epilogue: silu(r*g)*(r*u) -> g_act
    #pragma unroll
    for (int mf = 0; mf < 2; mf++) {
        int rl0 = wm * 32 + mf * 16 + gid;
        int rl1 = rl0 + 8;
        float rr0 = rws[rl0], rr1 = rws[rl1];
        float* p0 = g_act + ((size_t)e * NT + row0 + rl0) * ID + n0 + wn * 32 + 2 * tg;
        float* p1 = g_act + ((size_t)e * NT + row0 + rl1) * ID + n0 + wn * 32 + 2 * tg;
        #pragma unroll
        for (int nf = 0; nf < 4; nf++) {
            float g0 = rr0 * accG[mf][nf][0], u0 = rr0 * accU[mf][nf][0];
            float g1 = rr0 * accG[mf][nf][1], u1 = rr0 * accU[mf][nf][1];
            float g2 = rr1 * accG[mf][nf][2], u2 = rr1 * accU[mf][nf][2];
            float g3 = rr1 * accG[mf][nf][3], u3 = rr1 * accU[mf][nf][3];
            *(float2*)(p0 + nf * 8) = make_float2(silu(g0) * u0, silu(g1) * u1);
            *(float2*)(p1 + nf * 8) = make_float2(silu(g2) * u2, silu(g3) * u3);
        }
    }
}

// =======================================================================
// down GEMM: BM=128 rows, BN=128 of H, K=ID=512, BK=32.
// 8 warps = 4(m) x 2(n); warp tile 32 x 64 (2m x 8n frags).
// smem floats: A[2][128*36] B[2][32*136]
// =======================================================================
constexpr int DN_A0 = 0, DN_A1 = 128 * 36;
constexpr int DN_B0 = 2 * 128 * 36, DN_B1 = DN_B0 + 32 * 136;
constexpr int DN_SMEM = (DN_B1 + 32 * 136) * 4;   // 71680 B

__global__ void __launch_bounds__(256)
k_down(const float* __restrict__ down_w, const float* __restrict__ sdown) {
    const int e    = blockIdx.z;
    const int c    = g_cnt[e];
    const int row0 = blockIdx.x * 128;
    if (row0 >= c) return;
    const int n0   = blockIdx.y * 128;

    extern __shared__ float sm[];
    const uint32_t sb = smem_u32(sm);
    const int tid = threadIdx.x;

    const float* Wd = (e == NEXP) ? sdown : down_w + (size_t)e * ID * HD;
    const float* Ab = g_act + ((size_t)e * NT + row0) * ID;

    auto load_stage = [&](int buf, int kk) {
        const int a_off = buf ? DN_A1 : DN_A0;
        const int b_off = buf ? DN_B1 : DN_B0;
        #pragma unroll
        for (int i = 0; i < 4; i++) {              // A: 128 x 32
            int lin = tid + i * 256;
            int r = lin >> 3, ch = lin & 7;
            cp16(sb + (a_off + r * 36 + ch * 4) * 4,
                 Ab + (size_t)r * ID + kk + ch * 4);
        }
        #pragma unroll
        for (int i = 0; i < 4; i++) {              // B: 32 x 128
            int lin = tid + i * 256;
            int k = lin >> 5, ch = lin & 31;
            cp16(sb + (b_off + k * 136 + ch * 4) * 4,
                 Wd + (size_t)(kk + k) * HD + n0 + ch * 4);
        }
    };

    const int wid = tid >> 5, lane = tid & 31;
    const int gid = lane >> 2, tg = lane & 3;
    const int wm = wid & 3, wn = wid >> 2;          // 4m x 2n (64 cols each)

    float acc[2][8][4] = {};

    load_stage(0, 0);
    CP_COMMIT();

    const int S = ID / 32;                           // 16 stages
    for (int s = 0; s < S; s++) {
        if (s + 1 < S) { load_stage((s + 1) & 1, (s + 1) * 32); CP_COMMIT(); CP_WAIT(1); }
        else           { CP_WAIT(0); }
        __syncthreads();

        const float* As = sm + ((s & 1) ? DN_A1 : DN_A0);
        const float* Bs = sm + ((s & 1) ? DN_B1 : DN_B0);

        #pragma unroll
        for (int kq = 0; kq < 4; kq++) {
            uint32_t a[2][4], b[8][2];
            #pragma unroll
            for (int mf = 0; mf < 2; mf++) {
                const float* ap = As + (wm * 32 + mf * 16 + gid) * 36 + kq * 8 + tg;
                a[mf][0] = f2tf32(ap[0]);
                a[mf][1] = f2tf32(ap[8 * 36]);
                a[mf][2] = f2tf32(ap[4]);
                a[mf][3] = f2tf32(ap[8 * 36 + 4]);
            }
            #pragma unroll
            for (int nf = 0; nf < 8; nf++) {
                const float* bp = Bs + (kq * 8 + tg) * 136 + wn * 64 + nf * 8 + gid;
                b[nf][0] = f2tf32(bp[0]); b[nf][1] = f2tf32(bp[4 * 136]);
            }
            #pragma unroll
            for (int mf = 0; mf < 2; mf++)
                #pragma unroll
                for (int nf = 0; nf < 8; nf++)
                    mma8(acc[mf][nf], a[mf], b[nf]);
        }
        __syncthreads();
    }

    // register epilogue -> g_dn (no weighting; combine sums later)
    #pragma unroll
    for (int mf = 0; mf < 2; mf++) {
        int rl0 = wm * 32 + mf * 16 + gid;
        int rl1 = rl0 + 8;
        float* p0 = g_dn + ((size_t)e * NT + row0 + rl0) * HD + n0 + wn * 64 + 2 * tg;
        float* p1 = g_dn + ((size_t)e * NT + row0 + rl1) * HD + n0 + wn * 64 + 2 * tg;
        #pragma unroll
        for (int nf = 0; nf < 8; nf++) {
            *(float2*)(p0 + nf * 8) = make_float2(acc[mf][nf][0], acc[mf][nf][1]);
            *(float2*)(p1 + nf * 8) = make_float2(acc[mf][nf][2], acc[mf][nf][3]);
        }
    }
}

// ---------------- combine: out[t] = shared row + 4 routed rows ----------------
__global__ void k_combine(float* __restrict__ out) {
    int t = blockIdx.x;
    const float4* sh = (const float4*)(g_dn + ((size_t)NEXP * NT + t) * HD);
    float4 a = sh[threadIdx.x];
    #pragma unroll
    for (int k = 0; k < TOPK; k++) {
        const float4* p = (const float4*)(g_dn + (size_t)g_pos[t * TOPK + k] * HD);
        float4 b = p[threadIdx.x];
        a.x += b.x; a.y += b.y; a.z += b.z; a.w += b.w;
    }
    ((float4*)out)[(size_t)t * 256 + threadIdx.x] = a;
}

// ---------------- launch ----------------
extern "C" void kernel_launch(void* const* d_in, const int* in_sizes, int n_in,
                              void* d_out, int out_size) {
    (void)in_sizes; (void)n_in; (void)out_size;
    const float* x     = (const float*)d_in[0];
    const float* rw    = (const float*)d_in[1];
    const float* gate  = (const float*)d_in[2];
    const float* up    = (const float*)d_in[3];
    const float* down  = (const float*)d_in[4];
    const float* sgate = (const float*)d_in[5];
    const float* sup   = (const float*)d_in[6];
    const float* sdown = (const float*)d_in[7];
    float* out = (float*)d_out;

    cudaFuncSetAttribute(k_gateup, cudaFuncAttributeMaxDynamicSharedMemorySize, GU_SMEM);
    cudaFuncSetAttribute(k_down,   cudaFuncAttributeMaxDynamicSharedMemorySize, DN_SMEM);

    k_init<<<8, 256>>>();
    k_router<<<NT, 512>>>(x, rw);
    k_gateup<<<dim3(NT / 128, ID / 64, NE), 256, GU_SMEM>>>(x, gate, up, sgate, sup);
    k_down  <<<dim3(NT / 128, HD / 128, NE), 256, DN_SMEM>>>(down, sdown);
    k_combine<<<NT, 256>>>(out);
}

// round 7
// speedup vs baseline: 2.8040x; 1.3362x over previous
#include <cuda_runtime.h>
#include <cuda_fp16.h>
#include <math.h>
#include <stdint.h>

// ---------------- problem constants ----------------
constexpr int HD   = 1024;
constexpr int ID   = 512;
constexpr int NEXP = 16;
constexpr int TOPK = 4;
constexpr int NT   = 2048;
constexpr int NE   = 17;          // 16 routed + shared pseudo-expert

// ---------------- device scratch (fp16 weights / activations) ----------------
__device__ int    g_cnt[NE];
__device__ int    g_tok[NE * NT];
__device__ float  g_rw [NE * NT];
__device__ int    g_pos[NT * TOPK];
__device__ __half g_wg[(size_t)NEXP * HD * ID];   // [e][h][i]
__device__ __half g_wu[(size_t)NEXP * HD * ID];
__device__ __half g_wd[(size_t)NEXP * ID * HD];   // [e][i][h]
__device__ __half g_sg[(size_t)HD * ID];
__device__ __half g_su[(size_t)HD * ID];
__device__ __half g_sd[(size_t)ID * HD];
__device__ __half g_xh[(size_t)NT * HD];
__device__ __half g_acth[(size_t)NE * NT * ID];   // gathered SwiGLU activations
__device__ __half g_dnh [(size_t)NE * NT * HD];   // per-(expert,slot) down outputs

// ---------------- helpers ----------------
__device__ __forceinline__ uint32_t smem_u32(const void* p) {
    uint32_t a;
    asm("{ .reg .u64 t; cvta.to.shared.u64 t, %1; cvt.u32.u64 %0, t; }" : "=r"(a) : "l"(p));
    return a;
}
__device__ __forceinline__ void cp16(uint32_t dst, const void* src) {
    asm volatile("cp.async.cg.shared.global [%0], [%1], 16;" :: "r"(dst), "l"(src));
}
#define CP_COMMIT() asm volatile("cp.async.commit_group;" ::: "memory")
#define CP_WAIT(n)  asm volatile("cp.async.wait_group %0;" :: "n"(n) : "memory")

#define LDSM4(r, a)                                                              \
    asm volatile("ldmatrix.sync.aligned.m8n8.x4.shared.b16 {%0,%1,%2,%3}, [%4];" \
        : "=r"((r)[0]), "=r"((r)[1]), "=r"((r)[2]), "=r"((r)[3]) : "r"(a))
#define LDSM4T(r, a)                                                             \
    asm volatile("ldmatrix.sync.aligned.m8n8.x4.trans.shared.b16 {%0,%1,%2,%3}, [%4];" \
        : "=r"((r)[0]), "=r"((r)[1]), "=r"((r)[2]), "=r"((r)[3]) : "r"(a))

// mma m16n8k16 f16 -> f32.  C: c0=(g,2tg) c1=(g,2tg+1) c2=(g+8,2tg) c3=(g+8,2tg+1)
__device__ __forceinline__ void mma16(float* c, const uint32_t* a, uint32_t b0, uint32_t b1) {
    asm volatile(
        "mma.sync.aligned.m16n8k16.row.col.f32.f16.f16.f32 "
        "{%0,%1,%2,%3}, {%4,%5,%6,%7}, {%8,%9}, {%0,%1,%2,%3};"
        : "+f"(c[0]), "+f"(c[1]), "+f"(c[2]), "+f"(c[3])
        : "r"(a[0]), "r"(a[1]), "r"(a[2]), "r"(a[3]), "r"(b0), "r"(b1));
}
__device__ __forceinline__ float silu(float g) { return g / (1.f + expf(-g)); }

// ---------------- fp32 -> fp16 convert (selector resolves __device__ dst) ----------------
__global__ void k_cvt(const float* __restrict__ s, int which, int n) {
    __half* d = (which == 0) ? g_wg : (which == 1) ? g_wu : (which == 2) ? g_wd
              : (which == 3) ? g_sg : (which == 4) ? g_su : (which == 5) ? g_sd : g_xh;
    int i = (blockIdx.x * blockDim.x + threadIdx.x) * 8;
    if (i >= n) return;
    float4 a = *(const float4*)(s + i);
    float4 b = *(const float4*)(s + i + 4);
    __half2 h0 = __floats2half2_rn(a.x, a.y);
    __half2 h1 = __floats2half2_rn(a.z, a.w);
    __half2 h2 = __floats2half2_rn(b.x, b.y);
    __half2 h3 = __floats2half2_rn(b.z, b.w);
    uint4 o;
    o.x = *(uint32_t*)&h0; o.y = *(uint32_t*)&h1;
    o.z = *(uint32_t*)&h2; o.w = *(uint32_t*)&h3;
    *(uint4*)(d + i) = o;
}

// ---------------- init ----------------
__global__ void k_init() {
    int idx = blockIdx.x * blockDim.x + threadIdx.x;
    if (idx < NE) g_cnt[idx] = (idx == NEXP) ? NT : 0;
    if (idx < NT) { g_tok[NEXP * NT + idx] = idx; g_rw[NEXP * NT + idx] = 1.0f; }
}

// ---------------- router: fp32 exact ----------------
__global__ void k_router(const float* __restrict__ x, const float* __restrict__ rw) {
    const int t    = blockIdx.x;
    const int wid  = threadIdx.x >> 5;
    const int lane = threadIdx.x & 31;
    __shared__ float sl[NEXP];

    const float* xr = x + (size_t)t * HD;
    float acc = 0.f;
    for (int h = lane; h < HD; h += 32)
        acc += xr[h] * rw[h * NEXP + wid];
    #pragma unroll
    for (int o = 16; o > 0; o >>= 1)
        acc += __shfl_down_sync(0xffffffffu, acc, o);
    if (lane == 0) sl[wid] = acc;
    __syncthreads();

    if (threadIdx.x == 0) {
        float v[NEXP]; bool used[NEXP];
        #pragma unroll
        for (int e = 0; e < NEXP; e++) { v[e] = 1.f / (1.f + expf(-sl[e])); used[e] = false; }
        #pragma unroll
        for (int k = 0; k < TOPK; k++) {
            int be = -1; float bv = -1.f;
            #pragma unroll
            for (int e = 0; e < NEXP; e++)
                if (!used[e] && v[e] > bv) { bv = v[e]; be = e; }
            used[be] = true;
            int j = atomicAdd(&g_cnt[be], 1);
            g_tok[be * NT + j] = t;
            g_rw [be * NT + j] = bv;
            g_pos[t * TOPK + k] = be * NT + j;
        }
    }
}

// =======================================================================
// gate/up: BM=128, BN=64 (G and U), BK=32, 4 warps (2m x 2n), warp 64x32.
// 3-stage cp.async.  smem halves: A[3][128*40]  Bg[3][32*72]  Bu[3][32*72]
// =======================================================================
constexpr int GU_ASTG = 128 * 40;           // halves per A stage
constexpr int GU_BSTG = 32 * 72;
constexpr int GU_SMEM = 1024 + (3 * GU_ASTG + 6 * GU_BSTG) * 2;   // 59392 B

__global__ void __launch_bounds__(128)
k_gateup() {
    const int e    = blockIdx.z;
    const int c    = g_cnt[e];
    const int row0 = blockIdx.x * 128;
    if (row0 >= c) return;
    const int n0   = blockIdx.y * 64;

    extern __shared__ char smc[];
    int*    toks = (int*)smc;
    float*  rws  = (float*)(smc + 512);
    __half* sA   = (__half*)(smc + 1024);
    __half* sG   = sA + 3 * GU_ASTG;
    __half* sU   = sG + 3 * GU_BSTG;
    const int tid = threadIdx.x;

    const __half* Wg = (e == NEXP) ? g_sg : g_wg + (size_t)e * HD * ID;
    const __half* Wu = (e == NEXP) ? g_su : g_wu + (size_t)e * HD * ID;

    if (tid < 128) {
        int r = row0 + tid;
        if (r < c) { toks[tid] = g_tok[e * NT + r]; rws[tid] = g_rw[e * NT + r]; }
        else       { toks[tid] = 0;                 rws[tid] = 0.f; }
    }
    __syncthreads();

    const uint32_t abA = smem_u32(sA), abG = smem_u32(sG), abU = smem_u32(sU);

    auto load_stage = [&](int buf, int kk) {
        uint32_t dA = abA + buf * GU_ASTG * 2;
        #pragma unroll
        for (int i = 0; i < 4; i++) {                 // A: 128 x 32h = 512 chunks
            int lin = tid + i * 128;
            int r = lin >> 2, q = lin & 3;
            cp16(dA + (r * 40 + q * 8) * 2, g_xh + (size_t)toks[r] * HD + kk + q * 8);
        }
        uint32_t dG = abG + buf * GU_BSTG * 2;
        uint32_t dU = abU + buf * GU_BSTG * 2;
        #pragma unroll
        for (int i = 0; i < 2; i++) {                 // Bg: 32 x 64h = 256 chunks
            int lin = tid + i * 128;
            int k = lin >> 3, ch = lin & 7;
            cp16(dG + (k * 72 + ch * 8) * 2, Wg + (size_t)(kk + k) * ID + n0 + ch * 8);
        }
        #pragma unroll
        for (int i = 0; i < 2; i++) {                 // Bu
            int lin = tid + i * 128;
            int k = lin >> 3, ch = lin & 7;
            cp16(dU + (k * 72 + ch * 8) * 2, Wu + (size_t)(kk + k) * ID + n0 + ch * 8);
        }
    };

    const int wid = tid >> 5, lane = tid & 31;
    const int gid = lane >> 2, tg = lane & 3;
    const int wm = wid & 1, wn = wid >> 1;
    const int l15 = lane & 15, l16 = lane >> 4;

    float accG[4][4][4] = {}, accU[4][4][4] = {};

    load_stage(0, 0);  CP_COMMIT();
    load_stage(1, 32); CP_COMMIT();

    const int S = HD / 32;   // 32 stages
    for (int s = 0; s < S; s++) {
        CP_WAIT(1);
        __syncthreads();
        if (s + 2 < S) load_stage((s + 2) % 3, (s + 2) * 32);
        CP_COMMIT();

        int buf = s % 3;
        uint32_t bA = abA + buf * GU_ASTG * 2;
        uint32_t bG = abG + buf * GU_BSTG * 2;
        uint32_t bU = abU + buf * GU_BSTG * 2;

        #pragma unroll
        for (int kq = 0; kq < 2; kq++) {
            uint32_t a[4][4], bg[2][4], bu[2][4];
            #pragma unroll
            for (int mf = 0; mf < 4; mf++)
                LDSM4(a[mf], bA + ((wm * 64 + mf * 16 + l15) * 40 + kq * 16 + l16 * 8) * 2);
            #pragma unroll
            for (int h = 0; h < 2; h++) {
                LDSM4T(bg[h], bG + ((kq * 16 + l15) * 72 + wn * 32 + h * 16 + l16 * 8) * 2);
                LDSM4T(bu[h], bU + ((kq * 16 + l15) * 72 + wn * 32 + h * 16 + l16 * 8) * 2);
            }
            #pragma unroll
            for (int mf = 0; mf < 4; mf++)
                #pragma unroll
                for (int h = 0; h < 2; h++) {
                    mma16(accG[mf][2 * h + 0], a[mf], bg[h][0], bg[h][1]);
                    mma16(accG[mf][2 * h + 1], a[mf], bg[h][2], bg[h][3]);
                    mma16(accU[mf][2 * h + 0], a[mf], bu[h][0], bu[h][1]);
                    mma16(accU[mf][2 * h + 1], a[mf], bu[h][2], bu[h][3]);
                }
        }
    }

    // epilogue: silu(r*g)*(r*u) -> g_acth (fp16)
    #pragma unroll
    for (int mf = 0; mf < 4; mf++) {
        int rl = wm * 64 + mf * 16 + gid;
        float rr0 = rws[rl], rr1 = rws[rl + 8];
        __half* p0 = g_acth + ((size_t)e * NT + row0 + rl)     * ID + n0 + wn * 32 + 2 * tg;
        __half* p1 = g_acth + ((size_t)e * NT + row0 + rl + 8) * ID + n0 + wn * 32 + 2 * tg;
        #pragma unroll
        for (int nf = 0; nf < 4; nf++) {
            float g0 = rr0 * accG[mf][nf][0], u0 = rr0 * accU[mf][nf][0];
            float g1 = rr0 * accG[mf][nf][1], u1 = rr0 * accU[mf][nf][1];
            float g2 = rr1 * accG[mf][nf][2], u2 = rr1 * accU[mf][nf][2];
            float g3 = rr1 * accG[mf][nf][3], u3 = rr1 * accU[mf][nf][3];
            *(__half2*)(p0 + nf * 8) = __floats2half2_rn(silu(g0) * u0, silu(g1) * u1);
            *(__half2*)(p1 + nf * 8) = __floats2half2_rn(silu(g2) * u2, silu(g3) * u3);
        }
    }
}

// =======================================================================
// down: BM=128, BN=128, BK=32, 4 warps (2m x 2n), warp 64x64.
// smem halves: A[3][128*40]  B[3][32*136]
// =======================================================================
constexpr int DN_ASTG = 128 * 40;
constexpr int DN_BSTG = 32 * 136;
constexpr int DN_SMEM = (3 * DN_ASTG + 3 * DN_BSTG) * 2;   // 56832 B

__global__ void __launch_bounds__(128)
k_down() {
    const int e    = blockIdx.z;
    const int c    = g_cnt[e];
    const int row0 = blockIdx.x * 128;
    if (row0 >= c) return;
    const int n0   = blockIdx.y * 128;

    extern __shared__ char smc[];
    __half* sA = (__half*)smc;
    __half* sB = sA + 3 * DN_ASTG;
    const int tid = threadIdx.x;

    const __half* Wd = (e == NEXP) ? g_sd : g_wd + (size_t)e * ID * HD;
    const __half* Ab = g_acth + ((size_t)e * NT + row0) * ID;

    const uint32_t abA = smem_u32(sA), abB = smem_u32(sB);

    auto load_stage = [&](int buf, int kk) {
        uint32_t dA = abA + buf * DN_ASTG * 2;
        #pragma unroll
        for (int i = 0; i < 4; i++) {                 // A: 128 x 32h
            int lin = tid + i * 128;
            int r = lin >> 2, q = lin & 3;
            cp16(dA + (r * 40 + q * 8) * 2, Ab + (size_t)r * ID + kk + q * 8);
        }
        uint32_t dB = abB + buf * DN_BSTG * 2;
        #pragma unroll
        for (int i = 0; i < 4; i++) {                 // B: 32 x 128h
            int lin = tid + i * 128;
            int k = lin >> 4, ch = lin & 15;
            cp16(dB + (k * 136 + ch * 8) * 2, Wd + (size_t)(kk + k) * HD + n0 + ch * 8);
        }
    };

    const int wid = tid >> 5, lane = tid & 31;
    const int gid = lane >> 2, tg = lane & 3;
    const int wm = wid & 1, wn = wid >> 1;
    const int l15 = lane & 15, l16 = lane >> 4;

    float acc[4][8][4] = {};

    load_stage(0, 0);  CP_COMMIT();
    load_stage(1, 32); CP_COMMIT();

    const int S = ID / 32;   // 16 stages
    for (int s = 0; s < S; s++) {
        CP_WAIT(1);
        __syncthreads();
        if (s + 2 < S) load_stage((s + 2) % 3, (s + 2) * 32);
        CP_COMMIT();

        int buf = s % 3;
        uint32_t bA = abA + buf * DN_ASTG * 2;
        uint32_t bB = abB + buf * DN_BSTG * 2;

        #pragma unroll
        for (int kq = 0; kq < 2; kq++) {
            uint32_t a[4][4], b[4][4];
            #pragma unroll
            for (int mf = 0; mf < 4; mf++)
                LDSM4(a[mf], bA + ((wm * 64 + mf * 16 + l15) * 40 + kq * 16 + l16 * 8) * 2);
            #pragma unroll
            for (int h = 0; h < 4; h++)
                LDSM4T(b[h], bB + ((kq * 16 + l15) * 136 + wn * 64 + h * 16 + l16 * 8) * 2);
            #pragma unroll
            for (int mf = 0; mf < 4; mf++)
                #pragma unroll
                for (int h = 0; h < 4; h++) {
                    mma16(acc[mf][2 * h + 0], a[mf], b[h][0], b[h][1]);
                    mma16(acc[mf][2 * h + 1], a[mf], b[h][2], b[h][3]);
                }
        }
    }

    // epilogue -> g_dnh (fp16)
    #pragma unroll
    for (int mf = 0; mf < 4; mf++) {
        int rl = wm * 64 + mf * 16 + gid;
        __half* p0 = g_dnh + ((size_t)e * NT + row0 + rl)     * HD + n0 + wn * 64 + 2 * tg;
        __half* p1 = g_dnh + ((size_t)e * NT + row0 + rl + 8) * HD + n0 + wn * 64 + 2 * tg;
        #pragma unroll
        for (int nf = 0; nf < 8; nf++) {
            *(__half2*)(p0 + nf * 8) = __floats2half2_rn(acc[mf][nf][0], acc[mf][nf][1]);
            *(__half2*)(p1 + nf * 8) = __floats2half2_rn(acc[mf][nf][2], acc[mf][nf][3]);
        }
    }
}

// ---------------- combine: out[t] = shared row + 4 routed rows (fp32) ----------------
__global__ void k_combine(float* __restrict__ out) {
    int t  = blockIdx.x;
    int c0 = threadIdx.x * 8;                         // 128 threads x 8 cols
    float acc[8];
    {
        const uint4 v = *(const uint4*)(g_dnh + ((size_t)NEXP * NT + t) * HD + c0);
        const __half2* h = (const __half2*)&v;
        #pragma unroll
        for (int j = 0; j < 4; j++) {
            float2 f = __half22float2(h[j]);
            acc[2 * j] = f.x; acc[2 * j + 1] = f.y;
        }
    }
    #pragma unroll
    for (int k = 0; k < TOPK; k++) {
        const uint4 v = *(const uint4*)(g_dnh + (size_t)g_pos[t * TOPK + k] * HD + c0);
        const __half2* h = (const __half2*)&v;
        #pragma unroll
        for (int j = 0; j < 4; j++) {
            float2 f = __half22float2(h[j]);
            acc[2 * j] += f.x; acc[2 * j + 1] += f.y;
        }
    }
    float* op = out + (size_t)t * HD + c0;
    *(float4*)op       = make_float4(acc[0], acc[1], acc[2], acc[3]);
    *(float4*)(op + 4) = make_float4(acc[4], acc[5], acc[6], acc[7]);
}

// ---------------- launch ----------------
extern "C" void kernel_launch(void* const* d_in, const int* in_sizes, int n_in,
                              void* d_out, int out_size) {
    (void)in_sizes; (void)n_in; (void)out_size;
    const float* x     = (const float*)d_in[0];
    const float* rw    = (const float*)d_in[1];
    const float* gate  = (const float*)d_in[2];
    const float* up    = (const float*)d_in[3];
    const float* down  = (const float*)d_in[4];
    const float* sgate = (const float*)d_in[5];
    const float* sup   = (const float*)d_in[6];
    const float* sdown = (const float*)d_in[7];
    float* out = (float*)d_out;

    cudaFuncSetAttribute(k_gateup, cudaFuncAttributeMaxDynamicSharedMemorySize, GU_SMEM);
    cudaFuncSetAttribute(k_down,   cudaFuncAttributeMaxDynamicSharedMemorySize, DN_SMEM);

    const int EW = NEXP * HD * ID;          // 8388608
    const int SW = HD * ID;                 // 524288
    const int XN = NT * HD;                 // 2097152

    k_cvt<<<EW / 2048, 256>>>(gate,  0, EW);
    k_cvt<<<EW / 2048, 256>>>(up,    1, EW);
    k_cvt<<<EW / 2048, 256>>>(down,  2, EW);
    k_cvt<<<SW / 2048, 256>>>(sgate, 3, SW);
    k_cvt<<<SW / 2048, 256>>>(sup,   4, SW);
    k_cvt<<<SW / 2048, 256>>>(sdown, 5, SW);
    k_cvt<<<XN / 2048, 256>>>(x,     6, XN);
    k_init<<<8, 256>>>();
    k_router<<<NT, 512>>>(x, rw);
    k_gateup<<<dim3(NT / 128, ID / 64, NE), 128, GU_SMEM>>>();
    k_down  <<<dim3(NT / 128, HD / 128, NE), 128, DN_SMEM>>>();
    k_combine<<<NT, 128>>>(out);
}

// round 9
// speedup vs baseline: 2.9527x; 1.0530x over previous
#include <cuda_runtime.h>
#include <cuda_fp16.h>
#include <math.h>
#include <stdint.h>

// ---------------- problem constants ----------------
constexpr int HD   = 1024;
constexpr int ID   = 512;
constexpr int NEXP = 16;
constexpr int TOPK = 4;
constexpr int NT   = 2048;
constexpr int NE   = 17;          // 16 routed + shared pseudo-expert

// ---------------- device scratch ----------------
__device__ int    g_cnt[NE];
__device__ int    g_tok[NE * NT];
__device__ float  g_rw [NE * NT];
__device__ int    g_pos[NT * TOPK];
__device__ __half g_xh[(size_t)NT * HD];
__device__ __half g_acth[(size_t)NE * NT * ID];   // gathered SwiGLU activations
__device__ __half g_dnh [(size_t)NE * NT * HD];   // per-(expert,slot) down outputs

// ---------------- helpers ----------------
__device__ __forceinline__ uint32_t smem_u32(const void* p) {
    uint32_t a;
    asm("{ .reg .u64 t; cvta.to.shared.u64 t, %1; cvt.u32.u64 %0, t; }" : "=r"(a) : "l"(p));
    return a;
}
__device__ __forceinline__ void cp16(uint32_t dst, const void* src) {
    asm volatile("cp.async.cg.shared.global [%0], [%1], 16;" :: "r"(dst), "l"(src));
}
#define CP_COMMIT() asm volatile("cp.async.commit_group;" ::: "memory")
#define CP_WAIT(n)  asm volatile("cp.async.wait_group %0;" :: "n"(n) : "memory")

#define LDSM4(r, a)                                                              \
    asm volatile("ldmatrix.sync.aligned.m8n8.x4.shared.b16 {%0,%1,%2,%3}, [%4];" \
        : "=r"((r)[0]), "=r"((r)[1]), "=r"((r)[2]), "=r"((r)[3]) : "r"(a))
#define LDSM4T(r, a)                                                             \
    asm volatile("ldmatrix.sync.aligned.m8n8.x4.trans.shared.b16 {%0,%1,%2,%3}, [%4];" \
        : "=r"((r)[0]), "=r"((r)[1]), "=r"((r)[2]), "=r"((r)[3]) : "r"(a))

// mma m16n8k16 f16 -> f32.  C: c0=(g,2tg) c1=(g,2tg+1) c2=(g+8,2tg) c3=(g+8,2tg+1)
__device__ __forceinline__ void mma16(float* c, const uint32_t* a, uint32_t b0, uint32_t b1) {
    asm volatile(
        "mma.sync.aligned.m16n8k16.row.col.f32.f16.f16.f32 "
        "{%0,%1,%2,%3}, {%4,%5,%6,%7}, {%8,%9}, {%0,%1,%2,%3};"
        : "+f"(c[0]), "+f"(c[1]), "+f"(c[2]), "+f"(c[3])
        : "r"(a[0]), "r"(a[1]), "r"(a[2]), "r"(a[3]), "r"(b0), "r"(b1));
}
__device__ __forceinline__ float silu(float g) { return g / (1.f + expf(-g)); }
__device__ __forceinline__ uint2 f4_to_h4(float4 v) {
    __half2 a = __floats2half2_rn(v.x, v.y);
    __half2 b = __floats2half2_rn(v.z, v.w);
    uint2 o;
    o.x = *(uint32_t*)&a; o.y = *(uint32_t*)&b;
    return o;
}

// ---------------- pre: convert x -> fp16, init counters / shared-expert slots ----------------
__global__ void k_pre(const float* __restrict__ x) {
    if (blockIdx.x == 0) {
        for (int j = threadIdx.x; j < NT; j += blockDim.x) {
            g_tok[NEXP * NT + j] = j;
            g_rw [NEXP * NT + j] = 1.0f;
        }
        if (threadIdx.x < NE) g_cnt[threadIdx.x] = (threadIdx.x == NEXP) ? NT : 0;
    }
    int i = (blockIdx.x * blockDim.x + threadIdx.x) * 8;     // grid 1024 * 256 * 8 = 2M
    float4 a = *(const float4*)(x + i);
    float4 b = *(const float4*)(x + i + 4);
    uint2 lo = f4_to_h4(a), hi = f4_to_h4(b);
    uint4 o; o.x = lo.x; o.y = lo.y; o.z = hi.x; o.w = hi.y;
    *(uint4*)(g_xh + i) = o;
}

// ---------------- router: fp32 exact ----------------
__global__ void k_router(const float* __restrict__ x, const float* __restrict__ rw) {
    const int t    = blockIdx.x;
    const int wid  = threadIdx.x >> 5;
    const int lane = threadIdx.x & 31;
    __shared__ float sl[NEXP];

    const float* xr = x + (size_t)t * HD;
    float acc = 0.f;
    for (int h = lane; h < HD; h += 32)
        acc += xr[h] * rw[h * NEXP + wid];
    #pragma unroll
    for (int o = 16; o > 0; o >>= 1)
        acc += __shfl_down_sync(0xffffffffu, acc, o);
    if (lane == 0) sl[wid] = acc;
    __syncthreads();

    if (threadIdx.x == 0) {
        float v[NEXP]; bool used[NEXP];
        #pragma unroll
        for (int e = 0; e < NEXP; e++) { v[e] = 1.f / (1.f + expf(-sl[e])); used[e] = false; }
        #pragma unroll
        for (int k = 0; k < TOPK; k++) {
            int be = -1; float bv = -1.f;
            #pragma unroll
            for (int e = 0; e < NEXP; e++)
                if (!used[e] && v[e] > bv) { bv = v[e]; be = e; }
            used[be] = true;
            int j = atomicAdd(&g_cnt[be], 1);
            g_tok[be * NT + j] = t;
            g_rw [be * NT + j] = bv;
            g_pos[t * TOPK + k] = be * NT + j;
        }
    }
}

// =======================================================================
// gate/up: BM=128, BN=64 (G and U), BK=32, 4 warps (2m x 2n), warp 64x32.
// A: fp16 cp.async 3-stage from g_xh.
// B: fp32 LDG -> reg cvt fp16 -> STS, double-buffered one stage ahead.
// smem: toks/rws 1KB | A[3][128*40]h | Bg[2][32*72]h | Bu[2][32*72]h
// =======================================================================
constexpr int GU_ASTG = 128 * 40;           // halves per A stage
constexpr int GU_BSTG = 32 * 72;            // halves per B buffer
constexpr int GU_SMEM = 1024 + (3 * GU_ASTG + 4 * GU_BSTG) * 2;   // 50176 B

__global__ void __launch_bounds__(128)
k_gateup(const float* __restrict__ gate_w, const float* __restrict__ up_w,
         const float* __restrict__ sgate,  const float* __restrict__ sup) {
    const int e    = blockIdx.z;
    const int c    = g_cnt[e];
    const int row0 = blockIdx.x * 128;
    if (row0 >= c) return;
    const int n0   = blockIdx.y * 64;

    extern __shared__ char smc[];
    int*    toks = (int*)smc;
    float*  rws  = (float*)(smc + 512);
    __half* sA   = (__half*)(smc + 1024);
    __half* sG   = sA + 3 * GU_ASTG;
    __half* sU   = sG + 2 * GU_BSTG;
    const int tid = threadIdx.x;

    const float* Wg = (e == NEXP) ? sgate : gate_w + (size_t)e * HD * ID;
    const float* Wu = (e == NEXP) ? sup   : up_w   + (size_t)e * HD * ID;

    if (tid < 128) {
        int r = row0 + tid;
        if (r < c) { toks[tid] = g_tok[e * NT + r]; rws[tid] = g_rw[e * NT + r]; }
        else       { toks[tid] = 0;                 rws[tid] = 0.f; }
    }
    __syncthreads();

    const uint32_t abA = smem_u32(sA);

    auto ldA = [&](int buf, int kk) {
        uint32_t dA = abA + buf * GU_ASTG * 2;
        #pragma unroll
        for (int i = 0; i < 4; i++) {                 // A: 128 x 32h = 512 chunks
            int lin = tid + i * 128;
            int r = lin >> 2, q = lin & 3;
            cp16(dA + (r * 40 + q * 8) * 2, g_xh + (size_t)toks[r] * HD + kk + q * 8);
        }
    };

    float4 wg4[4], wu4[4];                            // B prefetch registers
    auto ldgB = [&](int kk) {
        #pragma unroll
        for (int i = 0; i < 4; i++) {                 // 512 float4 over 128 threads
            int lin = tid + i * 128;
            int k = lin >> 4, n4 = lin & 15;
            wg4[i] = *(const float4*)(Wg + (size_t)(kk + k) * ID + n0 + n4 * 4);
            wu4[i] = *(const float4*)(Wu + (size_t)(kk + k) * ID + n0 + n4 * 4);
        }
    };
    auto stsB = [&](int buf) {
        #pragma unroll
        for (int i = 0; i < 4; i++) {
            int lin = tid + i * 128;
            int k = lin >> 4, n4 = lin & 15;
            *(uint2*)(sG + buf * GU_BSTG + k * 72 + n4 * 4) = f4_to_h4(wg4[i]);
            *(uint2*)(sU + buf * GU_BSTG + k * 72 + n4 * 4) = f4_to_h4(wu4[i]);
        }
    };

    const int wid = tid >> 5, lane = tid & 31;
    const int gid = lane >> 2, tg = lane & 3;
    const int wm = wid & 1, wn = wid >> 1;
    const int l15 = lane & 15, l16 = lane >> 4;
    const uint32_t abG = smem_u32(sG), abU = smem_u32(sU);

    float accG[4][4][4] = {}, accU[4][4][4] = {};

    // prologue
    ldA(0, 0);  CP_COMMIT();
    ldgB(0);    stsB(0);
    ldA(1, 32); CP_COMMIT();
    ldgB(32);

    const int S = HD / 32;   // 32 stages
    for (int s = 0; s < S; s++) {
        if (s + 1 < S) { CP_WAIT(1); } else { CP_WAIT(0); }
        __syncthreads();
        if (s + 1 < S) stsB((s + 1) & 1);
        if (s + 2 < S) { ldA((s + 2) % 3, (s + 2) * 32); CP_COMMIT(); ldgB((s + 2) * 32); }

        uint32_t bA = abA + (s % 3) * GU_ASTG * 2;
        uint32_t bG = abG + (s & 1) * GU_BSTG * 2;
        uint32_t bU = abU + (s & 1) * GU_BSTG * 2;

        #pragma unroll
        for (int kq = 0; kq < 2; kq++) {
            uint32_t a[4][4], bg[2][4], bu[2][4];
            #pragma unroll
            for (int mf = 0; mf < 4; mf++)
                LDSM4(a[mf], bA + ((wm * 64 + mf * 16 + l15) * 40 + kq * 16 + l16 * 8) * 2);
            #pragma unroll
            for (int h = 0; h < 2; h++) {
                LDSM4T(bg[h], bG + ((kq * 16 + l15) * 72 + wn * 32 + h * 16 + l16 * 8) * 2);
                LDSM4T(bu[h], bU + ((kq * 16 + l15) * 72 + wn * 32 + h * 16 + l16 * 8) * 2);
            }
            #pragma unroll
            for (int mf = 0; mf < 4; mf++)
                #pragma unroll
                for (int h = 0; h < 2; h++) {
                    mma16(accG[mf][2 * h + 0], a[mf], bg[h][0], bg[h][1]);
                    mma16(accG[mf][2 * h + 1], a[mf], bg[h][2], bg[h][3]);
                    mma16(accU[mf][2 * h + 0], a[mf], bu[h][0], bu[h][1]);
                    mma16(accU[mf][2 * h + 1], a[mf], bu[h][2], bu[h][3]);
                }
        }
        __syncthreads();
    }

    // epilogue: silu(r*g)*(r*u) -> g_acth (fp16)
    #pragma unroll
    for (int mf = 0; mf < 4; mf++) {
        int rl = wm * 64 + mf * 16 + gid;
        float rr0 = rws[rl], rr1 = rws[rl + 8];
        __half* p0 = g_acth + ((size_t)e * NT + row0 + rl)     * ID + n0 + wn * 32 + 2 * tg;
        __half* p1 = g_acth + ((size_t)e * NT + row0 + rl + 8) * ID + n0 + wn * 32 + 2 * tg;
        #pragma unroll
        for (int nf = 0; nf < 4; nf++) {
            float g0 = rr0 * accG[mf][nf][0], u0 = rr0 * accU[mf][nf][0];
            float g1 = rr0 * accG[mf][nf][1], u1 = rr0 * accU[mf][nf][1];
            float g2 = rr1 * accG[mf][nf][2], u2 = rr1 * accU[mf][nf][2];
            float g3 = rr1 * accG[mf][nf][3], u3 = rr1 * accU[mf][nf][3];
            *(__half2*)(p0 + nf * 8) = __floats2half2_rn(silu(g0) * u0, silu(g1) * u1);
            *(__half2*)(p1 + nf * 8) = __floats2half2_rn(silu(g2) * u2, silu(g3) * u3);
        }
    }
}

// =======================================================================
// down: BM=128, BN=128, BK=32, 4 warps (2m x 2n), warp 64x64.
// A: fp16 cp.async 3-stage from g_acth.  B: fp32 LDG -> reg cvt -> STS, 2-buf.
// smem: A[3][128*40]h | B[2][32*136]h
// =======================================================================
constexpr int DN_ASTG = 128 * 40;
constexpr int DN_BSTG = 32 * 136;
constexpr int DN_SMEM = (3 * DN_ASTG + 2 * DN_BSTG) * 2;   // 48128 B

__global__ void __launch_bounds__(128)
k_down(const float* __restrict__ down_w, const float* __restrict__ sdown) {
    const int e    = blockIdx.z;
    const int c    = g_cnt[e];
    const int row0 = blockIdx.x * 128;
    if (row0 >= c) return;
    const int n0   = blockIdx.y * 128;

    extern __shared__ char smc[];
    __half* sA = (__half*)smc;
    __half* sB = sA + 3 * DN_ASTG;
    const int tid = threadIdx.x;

    const float* Wd = (e == NEXP) ? sdown : down_w + (size_t)e * ID * HD;
    const __half* Ab = g_acth + ((size_t)e * NT + row0) * ID;

    const uint32_t abA = smem_u32(sA), abB = smem_u32(sB);

    auto ldA = [&](int buf, int kk) {
        uint32_t dA = abA + buf * DN_ASTG * 2;
        #pragma unroll
        for (int i = 0; i < 4; i++) {                 // A: 128 x 32h
            int lin = tid + i * 128;
            int r = lin >> 2, q = lin & 3;
            cp16(dA + (r * 40 + q * 8) * 2, Ab + (size_t)r * ID + kk + q * 8);
        }
    };

    float4 wd4[8];                                    // B prefetch: 1024 float4 / 128 thr
    auto ldgB = [&](int kk) {
        #pragma unroll
        for (int i = 0; i < 8; i++) {
            int lin = tid + i * 128;
            int k = lin >> 5, n4 = lin & 31;
            wd4[i] = *(const float4*)(Wd + (size_t)(kk + k) * HD + n0 + n4 * 4);
        }
    };
    auto stsB = [&](int buf) {
        #pragma unroll
        for (int i = 0; i < 8; i++) {
            int lin = tid + i * 128;
            int k = lin >> 5, n4 = lin & 31;
            *(uint2*)(sB + buf * DN_BSTG + k * 136 + n4 * 4) = f4_to_h4(wd4[i]);
        }
    };

    const int wid = tid >> 5, lane = tid & 31;
    const int gid = lane >> 2, tg = lane & 3;
    const int wm = wid & 1, wn = wid >> 1;
    const int l15 = lane & 15, l16 = lane >> 4;

    float acc[4][8][4] = {};

    ldA(0, 0);  CP_COMMIT();
    ldgB(0);    stsB(0);
    ldA(1, 32); CP_COMMIT();
    ldgB(32);

    const int S = ID / 32;   // 16 stages
    for (int s = 0; s < S; s++) {
        if (s + 1 < S) { CP_WAIT(1); } else { CP_WAIT(0); }
        __syncthreads();
        if (s + 1 < S) stsB((s + 1) & 1);
        if (s + 2 < S) { ldA((s + 2) % 3, (s + 2) * 32); CP_COMMIT(); ldgB((s + 2) * 32); }

        uint32_t bA = abA + (s % 3) * DN_ASTG * 2;
        uint32_t bB = abB + (s & 1) * DN_BSTG * 2;

        #pragma unroll
        for (int kq = 0; kq < 2; kq++) {
            uint32_t a[4][4], b[4][4];
            #pragma unroll
            for (int mf = 0; mf < 4; mf++)
                LDSM4(a[mf], bA + ((wm * 64 + mf * 16 + l15) * 40 + kq * 16 + l16 * 8) * 2);
            #pragma unroll
            for (int h = 0; h < 4; h++)
                LDSM4T(b[h], bB + ((kq * 16 + l15) * 136 + wn * 64 + h * 16 + l16 * 8) * 2);
            #pragma unroll
            for (int mf = 0; mf < 4; mf++)
                #pragma unroll
                for (int h = 0; h < 4; h++) {
                    mma16(acc[mf][2 * h + 0], a[mf], b[h][0], b[h][1]);
                    mma16(acc[mf][2 * h + 1], a[mf], b[h][2], b[h][3]);
                }
        }
        __syncthreads();
    }

    // epilogue -> g_dnh (fp16)
    #pragma unroll
    for (int mf = 0; mf < 4; mf++) {
        int rl = wm * 64 + mf * 16 + gid;
        __half* p0 = g_dnh + ((size_t)e * NT + row0 + rl)     * HD + n0 + wn * 64 + 2 * tg;
        __half* p1 = g_dnh + ((size_t)e * NT + row0 + rl + 8) * HD + n0 + wn * 64 + 2 * tg;
        #pragma unroll
        for (int nf = 0; nf < 8; nf++) {
            *(__half2*)(p0 + nf * 8) = __floats2half2_rn(acc[mf][nf][0], acc[mf][nf][1]);
            *(__half2*)(p1 + nf * 8) = __floats2half2_rn(acc[mf][nf][2], acc[mf][nf][3]);
        }
    }
}

// ---------------- combine: out[t] = shared row + 4 routed rows (fp32) ----------------
__global__ void k_combine(float* __restrict__ out) {
    int t  = blockIdx.x;
    int c0 = threadIdx.x * 8;                         // 128 threads x 8 cols
    float acc[8];
    {
        const uint4 v = *(const uint4*)(g_dnh + ((size_t)NEXP * NT + t) * HD + c0);
        const __half2* h = (const __half2*)&v;
        #pragma unroll
        for (int j = 0; j < 4; j++) {
            float2 f = __half22float2(h[j]);
            acc[2 * j] = f.x; acc[2 * j + 1] = f.y;
        }
    }
    #pragma unroll
    for (int k = 0; k < TOPK; k++) {
        const uint4 v = *(const uint4*)(g_dnh + (size_t)g_pos[t * TOPK + k] * HD + c0);
        const __half2* h = (const __half2*)&v;
        #pragma unroll
        for (int j = 0; j < 4; j++) {
            float2 f = __half22float2(h[j]);
            acc[2 * j] += f.x; acc[2 * j + 1] += f.y;
        }
    }
    float* op = out + (size_t)t * HD + c0;
    *(float4*)op       = make_float4(acc[0], acc[1], acc[2], acc[3]);
    *(float4*)(op + 4) = make_float4(acc[4], acc[5], acc[6], acc[7]);
}

// ---------------- launch ----------------
extern "C" void kernel_launch(void* const* d_in, const int* in_sizes, int n_in,
                              void* d_out, int out_size) {
    (void)in_sizes; (void)n_in; (void)out_size;
    const float* x     = (const float*)d_in[0];
    const float* rw    = (const float*)d_in[1];
    const float* gate  = (const float*)d_in[2];
    const float* up    = (const float*)d_in[3];
    const float* down  = (const float*)d_in[4];
    const float* sgate = (const float*)d_in[5];
    const float* sup   = (const float*)d_in[6];
    const float* sdown = (const float*)d_in[7];
    float* out = (float*)d_out;

    cudaFuncSetAttribute(k_gateup, cudaFuncAttributeMaxDynamicSharedMemorySize, GU_SMEM);
    cudaFuncSetAttribute(k_down,   cudaFuncAttributeMaxDynamicSharedMemorySize, DN_SMEM);

    k_pre<<<NT * HD / 2048, 256>>>(x);
    k_router<<<NT, 512>>>(x, rw);
    k_gateup<<<dim3(NT / 128, ID / 64, NE), 128, GU_SMEM>>>(gate, up, sgate, sup);
    k_down  <<<dim3(NT / 128, HD / 128, NE), 128, DN_SMEM>>>(down, sdown);
    k_combine<<<NT, 128>>>(out);
}

// round 11
// speedup vs baseline: 3.0246x; 1.0244x over previous
#include <cuda_runtime.h>
#include <cuda_fp16.h>
#include <math.h>
#include <stdint.h>

// ---------------- problem constants ----------------
constexpr int HD   = 1024;
constexpr int ID   = 512;
constexpr int NEXP = 16;
constexpr int TOPK = 4;
constexpr int NT   = 2048;
constexpr int NE   = 17;          // 16 routed + shared pseudo-expert

// ---------------- device scratch ----------------
__device__ int    g_cnt[NE];
__device__ int    g_tok[NE * NT];
__device__ float  g_rw [NE * NT];
__device__ int    g_pos[NT * TOPK];
__device__ __half g_xh[(size_t)NT * HD];
__device__ __half g_acth[(size_t)NE * NT * ID];   // gathered SwiGLU activations
__device__ __half g_dnh [(size_t)NE * NT * HD];   // per-(expert,slot) down outputs

// ---------------- helpers ----------------
__device__ __forceinline__ uint32_t smem_u32(const void* p) {
    uint32_t a;
    asm("{ .reg .u64 t; cvta.to.shared.u64 t, %1; cvt.u32.u64 %0, t; }" : "=r"(a) : "l"(p));
    return a;
}
__device__ __forceinline__ void cp16(uint32_t dst, const void* src) {
    asm volatile("cp.async.cg.shared.global [%0], [%1], 16;" :: "r"(dst), "l"(src));
}
#define CP_COMMIT() asm volatile("cp.async.commit_group;" ::: "memory")
#define CP_WAIT(n)  asm volatile("cp.async.wait_group %0;" :: "n"(n) : "memory")

#define LDSM4(r, a)                                                              \
    asm volatile("ldmatrix.sync.aligned.m8n8.x4.shared.b16 {%0,%1,%2,%3}, [%4];" \
        : "=r"((r)[0]), "=r"((r)[1]), "=r"((r)[2]), "=r"((r)[3]) : "r"(a))
#define LDSM4T(r, a)                                                             \
    asm volatile("ldmatrix.sync.aligned.m8n8.x4.trans.shared.b16 {%0,%1,%2,%3}, [%4];" \
        : "=r"((r)[0]), "=r"((r)[1]), "=r"((r)[2]), "=r"((r)[3]) : "r"(a))

// mma m16n8k16 f16 -> f32.  C: c0=(g,2tg) c1=(g,2tg+1) c2=(g+8,2tg) c3=(g+8,2tg+1)
__device__ __forceinline__ void mma16(float* c, const uint32_t* a, uint32_t b0, uint32_t b1) {
    asm volatile(
        "mma.sync.aligned.m16n8k16.row.col.f32.f16.f16.f32 "
        "{%0,%1,%2,%3}, {%4,%5,%6,%7}, {%8,%9}, {%0,%1,%2,%3};"
        : "+f"(c[0]), "+f"(c[1]), "+f"(c[2]), "+f"(c[3])
        : "r"(a[0]), "r"(a[1]), "r"(a[2]), "r"(a[3]), "r"(b0), "r"(b1));
}
__device__ __forceinline__ float silu(float g) { return g / (1.f + expf(-g)); }
__device__ __forceinline__ uint2 f4_to_h4(float4 v) {
    __half2 a = __floats2half2_rn(v.x, v.y);
    __half2 b = __floats2half2_rn(v.z, v.w);
    uint2 o;
    o.x = *(uint32_t*)&a; o.y = *(uint32_t*)&b;
    return o;
}

// ---------------- pre: convert x -> fp16, init counters / shared-expert slots ----------------
__global__ void k_pre(const float* __restrict__ x) {
    if (blockIdx.x == 0) {
        for (int j = threadIdx.x; j < NT; j += blockDim.x) {
            g_tok[NEXP * NT + j] = j;
            g_rw [NEXP * NT + j] = 1.0f;
        }
        if (threadIdx.x < NE) g_cnt[threadIdx.x] = (threadIdx.x == NEXP) ? NT : 0;
    }
    int i = (blockIdx.x * blockDim.x + threadIdx.x) * 8;     // grid 1024 * 256 * 8 = 2M
    float4 a = *(const float4*)(x + i);
    float4 b = *(const float4*)(x + i + 4);
    uint2 lo = f4_to_h4(a), hi = f4_to_h4(b);
    uint4 o; o.x = lo.x; o.y = lo.y; o.z = hi.x; o.w = hi.y;
    *(uint4*)(g_xh + i) = o;
}

// ---------------- router: fp32 exact ----------------
__global__ void k_router(const float* __restrict__ x, const float* __restrict__ rw) {
    const int t    = blockIdx.x;
    const int wid  = threadIdx.x >> 5;
    const int lane = threadIdx.x & 31;
    __shared__ float sl[NEXP];

    const float* xr = x + (size_t)t * HD;
    float acc = 0.f;
    for (int h = lane; h < HD; h += 32)
        acc += xr[h] * rw[h * NEXP + wid];
    #pragma unroll
    for (int o = 16; o > 0; o >>= 1)
        acc += __shfl_down_sync(0xffffffffu, acc, o);
    if (lane == 0) sl[wid] = acc;
    __syncthreads();

    if (threadIdx.x == 0) {
        float v[NEXP]; bool used[NEXP];
        #pragma unroll
        for (int e = 0; e < NEXP; e++) { v[e] = 1.f / (1.f + expf(-sl[e])); used[e] = false; }
        #pragma unroll
        for (int k = 0; k < TOPK; k++) {
            int be = -1; float bv = -1.f;
            #pragma unroll
            for (int e = 0; e < NEXP; e++)
                if (!used[e] && v[e] > bv) { bv = v[e]; be = e; }
            used[be] = true;
            int j = atomicAdd(&g_cnt[be], 1);
            g_tok[be * NT + j] = t;
            g_rw [be * NT + j] = bv;
            g_pos[t * TOPK + k] = be * NT + j;
        }
    }
}

// =======================================================================
// gate/up: BM=128, BN=64 (G and U), BK=32, 256 thr / 8 warps (4m x 2n),
// warp tile 32x32 for G and 32x32 for U.
// A: fp16 cp.async 3-stage.  B: fp32 LDG -> reg cvt -> STS, 2-buf.
// smem: toks/rws 1KB | A[3][128*40]h | Bg[2][32*72]h | Bu[2][32*72]h
// =======================================================================
constexpr int GU_ASTG = 128 * 40;
constexpr int GU_BSTG = 32 * 72;
constexpr int GU_SMEM = 1024 + (3 * GU_ASTG + 4 * GU_BSTG) * 2;   // 50176 B

__global__ void __launch_bounds__(256, 2)
k_gateup(const float* __restrict__ gate_w, const float* __restrict__ up_w,
         const float* __restrict__ sgate,  const float* __restrict__ sup) {
    const int e    = blockIdx.z;
    const int c    = g_cnt[e];
    const int row0 = blockIdx.x * 128;
    if (row0 >= c) return;
    const int n0   = blockIdx.y * 64;

    extern __shared__ char smc[];
    int*    toks = (int*)smc;
    float*  rws  = (float*)(smc + 512);
    __half* sA   = (__half*)(smc + 1024);
    __half* sG   = sA + 3 * GU_ASTG;
    __half* sU   = sG + 2 * GU_BSTG;
    const int tid = threadIdx.x;

    const float* Wg = (e == NEXP) ? sgate : gate_w + (size_t)e * HD * ID;
    const float* Wu = (e == NEXP) ? sup   : up_w   + (size_t)e * HD * ID;

    if (tid < 128) {
        int r = row0 + tid;
        if (r < c) { toks[tid] = g_tok[e * NT + r]; rws[tid] = g_rw[e * NT + r]; }
        else       { toks[tid] = 0;                 rws[tid] = 0.f; }
    }
    __syncthreads();

    const uint32_t abA = smem_u32(sA);

    auto ldA = [&](int buf, int kk) {
        uint32_t dA = abA + buf * GU_ASTG * 2;
        #pragma unroll
        for (int i = 0; i < 2; i++) {                 // A: 128 x 32h = 512 16B chunks
            int lin = tid + i * 256;
            int r = lin >> 2, q = lin & 3;
            cp16(dA + (r * 40 + q * 8) * 2, g_xh + (size_t)toks[r] * HD + kk + q * 8);
        }
    };

    float4 wg4[2], wu4[2];                            // B prefetch registers
    auto ldgB = [&](int kk) {
        #pragma unroll
        for (int i = 0; i < 2; i++) {                 // 512 float4 over 256 threads
            int lin = tid + i * 256;
            int k = lin >> 4, n4 = lin & 15;
            wg4[i] = *(const float4*)(Wg + (size_t)(kk + k) * ID + n0 + n4 * 4);
            wu4[i] = *(const float4*)(Wu + (size_t)(kk + k) * ID + n0 + n4 * 4);
        }
    };
    auto stsB = [&](int buf) {
        #pragma unroll
        for (int i = 0; i < 2; i++) {
            int lin = tid + i * 256;
            int k = lin >> 4, n4 = lin & 15;
            *(uint2*)(sG + buf * GU_BSTG + k * 72 + n4 * 4) = f4_to_h4(wg4[i]);
            *(uint2*)(sU + buf * GU_BSTG + k * 72 + n4 * 4) = f4_to_h4(wu4[i]);
        }
    };

    const int wid = tid >> 5, lane = tid & 31;
    const int gid = lane >> 2, tg = lane & 3;
    const int wm = wid & 3, wn = wid >> 2;            // 4m x 2n
    const int l15 = lane & 15, l16 = lane >> 4;
    const uint32_t abG = smem_u32(sG), abU = smem_u32(sU);

    float accG[2][4][4] = {}, accU[2][4][4] = {};

    // prologue
    ldA(0, 0);  CP_COMMIT();
    ldgB(0);    stsB(0);
    ldA(1, 32); CP_COMMIT();
    ldgB(32);

    const int S = HD / 32;   // 32 stages
    for (int s = 0; s < S; s++) {
        if (s + 1 < S) { CP_WAIT(1); } else { CP_WAIT(0); }
        __syncthreads();
        if (s + 1 < S) stsB((s + 1) & 1);
        if (s + 2 < S) { ldA((s + 2) % 3, (s + 2) * 32); CP_COMMIT(); ldgB((s + 2) * 32); }

        uint32_t bA = abA + (s % 3) * GU_ASTG * 2;
        uint32_t bG = abG + (s & 1) * GU_BSTG * 2;
        uint32_t bU = abU + (s & 1) * GU_BSTG * 2;

        #pragma unroll
        for (int kq = 0; kq < 2; kq++) {
            uint32_t a[2][4], bg[2][4], bu[2][4];
            #pragma unroll
            for (int mf = 0; mf < 2; mf++)
                LDSM4(a[mf], bA + ((wm * 32 + mf * 16 + l15) * 40 + kq * 16 + l16 * 8) * 2);
            #pragma unroll
            for (int h = 0; h < 2; h++) {
                LDSM4T(bg[h], bG + ((kq * 16 + l15) * 72 + wn * 32 + h * 16 + l16 * 8) * 2);
                LDSM4T(bu[h], bU + ((kq * 16 + l15) * 72 + wn * 32 + h * 16 + l16 * 8) * 2);
            }
            #pragma unroll
            for (int mf = 0; mf < 2; mf++)
                #pragma unroll
                for (int h = 0; h < 2; h++) {
                    mma16(accG[mf][2 * h + 0], a[mf], bg[h][0], bg[h][1]);
                    mma16(accG[mf][2 * h + 1], a[mf], bg[h][2], bg[h][3]);
                    mma16(accU[mf][2 * h + 0], a[mf], bu[h][0], bu[h][1]);
                    mma16(accU[mf][2 * h + 1], a[mf], bu[h][2], bu[h][3]);
                }
        }
        __syncthreads();
    }

    // epilogue: silu(r*g)*(r*u) -> g_acth (fp16)
    #pragma unroll
    for (int mf = 0; mf < 2; mf++) {
        int rl = wm * 32 + mf * 16 + gid;
        float rr0 = rws[rl], rr1 = rws[rl + 8];
        __half* p0 = g_acth + ((size_t)e * NT + row0 + rl)     * ID + n0 + wn * 32 + 2 * tg;
        __half* p1 = g_acth + ((size_t)e * NT + row0 + rl + 8) * ID + n0 + wn * 32 + 2 * tg;
        #pragma unroll
        for (int nf = 0; nf < 4; nf++) {
            float g0 = rr0 * accG[mf][nf][0], u0 = rr0 * accU[mf][nf][0];
            float g1 = rr0 * accG[mf][nf][1], u1 = rr0 * accU[mf][nf][1];
            float g2 = rr1 * accG[mf][nf][2], u2 = rr1 * accU[mf][nf][2];
            float g3 = rr1 * accG[mf][nf][3], u3 = rr1 * accU[mf][nf][3];
            *(__half2*)(p0 + nf * 8) = __floats2half2_rn(silu(g0) * u0, silu(g1) * u1);
            *(__half2*)(p1 + nf * 8) = __floats2half2_rn(silu(g2) * u2, silu(g3) * u3);
        }
    }
}

// =======================================================================
// down: BM=128, BN=128, BK=32, 256 thr / 8 warps (4m x 2n), warp tile 32x64.
// A: fp16 cp.async 3-stage.  B: fp32 LDG -> reg cvt -> STS, 2-buf.
// smem: A[3][128*40]h | B[2][32*136]h
// =======================================================================
constexpr int DN_ASTG = 128 * 40;
constexpr int DN_BSTG = 32 * 136;
constexpr int DN_SMEM = (3 * DN_ASTG + 2 * DN_BSTG) * 2;   // 48128 B

__global__ void __launch_bounds__(256, 2)
k_down(const float* __restrict__ down_w, const float* __restrict__ sdown) {
    const int e    = blockIdx.z;
    const int c    = g_cnt[e];
    const int row0 = blockIdx.x * 128;
    if (row0 >= c) return;
    const int n0   = blockIdx.y * 128;

    extern __shared__ char smc[];
    __half* sA = (__half*)smc;
    __half* sB = sA + 3 * DN_ASTG;
    const int tid = threadIdx.x;

    const float* Wd = (e == NEXP) ? sdown : down_w + (size_t)e * ID * HD;
    const __half* Ab = g_acth + ((size_t)e * NT + row0) * ID;

    const uint32_t abA = smem_u32(sA), abB = smem_u32(sB);

    auto ldA = [&](int buf, int kk) {
        uint32_t dA = abA + buf * DN_ASTG * 2;
        #pragma unroll
        for (int i = 0; i < 2; i++) {                 // A: 128 x 32h
            int lin = tid + i * 256;
            int r = lin >> 2, q = lin & 3;
            cp16(dA + (r * 40 + q * 8) * 2, Ab + (size_t)r * ID + kk + q * 8);
        }
    };

    float4 wd4[4];                                    // B prefetch: 1024 float4 / 256 thr
    auto ldgB = [&](int kk) {
        #pragma unroll
        for (int i = 0; i < 4; i++) {
            int lin = tid + i * 256;
            int k = lin >> 5, n4 = lin & 31;
            wd4[i] = *(const float4*)(Wd + (size_t)(kk + k) * HD + n0 + n4 * 4);
        }
    };
    auto stsB = [&](int buf) {
        #pragma unroll
        for (int i = 0; i < 4; i++) {
            int lin = tid + i * 256;
            int k = lin >> 5, n4 = lin & 31;
            *(uint2*)(sB + buf * DN_BSTG + k * 136 + n4 * 4) = f4_to_h4(wd4[i]);
        }
    };

    const int wid = tid >> 5, lane = tid & 31;
    const int gid = lane >> 2, tg = lane & 3;
    const int wm = wid & 3, wn = wid >> 2;            // 4m x 2n
    const int l15 = lane & 15, l16 = lane >> 4;

    float acc[2][8][4] = {};

    ldA(0, 0);  CP_COMMIT();
    ldgB(0);    stsB(0);
    ldA(1, 32); CP_COMMIT();
    ldgB(32);

    const int S = ID / 32;   // 16 stages
    for (int s = 0; s < S; s++) {
        if (s + 1 < S) { CP_WAIT(1); } else { CP_WAIT(0); }
        __syncthreads();
        if (s + 1 < S) stsB((s + 1) & 1);
        if (s + 2 < S) { ldA((s + 2) % 3, (s + 2) * 32); CP_COMMIT(); ldgB((s + 2) * 32); }

        uint32_t bA = abA + (s % 3) * DN_ASTG * 2;
        uint32_t bB = abB + (s & 1) * DN_BSTG * 2;

        #pragma unroll
        for (int kq = 0; kq < 2; kq++) {
            uint32_t a[2][4], b[4][4];
            #pragma unroll
            for (int mf = 0; mf < 2; mf++)
                LDSM4(a[mf], bA + ((wm * 32 + mf * 16 + l15) * 40 + kq * 16 + l16 * 8) * 2);
            #pragma unroll
            for (int h = 0; h < 4; h++)
                LDSM4T(b[h], bB + ((kq * 16 + l15) * 136 + wn * 64 + h * 16 + l16 * 8) * 2);
            #pragma unroll
            for (int mf = 0; mf < 2; mf++)
                #pragma unroll
                for (int h = 0; h < 4; h++) {
                    mma16(acc[mf][2 * h + 0], a[mf], b[h][0], b[h][1]);
                    mma16(acc[mf][2 * h + 1], a[mf], b[h][2], b[h][3]);
                }
        }
        __syncthreads();
    }

    // epilogue -> g_dnh (fp16)
    #pragma unroll
    for (int mf = 0; mf < 2; mf++) {
        int rl = wm * 32 + mf * 16 + gid;
        __half* p0 = g_dnh + ((size_t)e * NT + row0 + rl)     * HD + n0 + wn * 64 + 2 * tg;
        __half* p1 = g_dnh + ((size_t)e * NT + row0 + rl + 8) * HD + n0 + wn * 64 + 2 * tg;
        #pragma unroll
        for (int nf = 0; nf < 8; nf++) {
            *(__half2*)(p0 + nf * 8) = __floats2half2_rn(acc[mf][nf][0], acc[mf][nf][1]);
            *(__half2*)(p1 + nf * 8) = __floats2half2_rn(acc[mf][nf][2], acc[mf][nf][3]);
        }
    }
}

// ---------------- combine: out[t] = shared row + 4 routed rows (fp32) ----------------
__global__ void k_combine(float* __restrict__ out) {
    int t  = blockIdx.x;
    int c0 = threadIdx.x * 8;                         // 128 threads x 8 cols
    float acc[8];
    {
        const uint4 v = *(const uint4*)(g_dnh + ((size_t)NEXP * NT + t) * HD + c0);
        const __half2* h = (const __half2*)&v;
        #pragma unroll
        for (int j = 0; j < 4; j++) {
            float2 f = __half22float2(h[j]);
            acc[2 * j] = f.x; acc[2 * j + 1] = f.y;
        }
    }
    #pragma unroll
    for (int k = 0; k < TOPK; k++) {
        const uint4 v = *(const uint4*)(g_dnh + (size_t)g_pos[t * TOPK + k] * HD + c0);
        const __half2* h = (const __half2*)&v;
        #pragma unroll
        for (int j = 0; j < 4; j++) {
            float2 f = __half22float2(h[j]);
            acc[2 * j] += f.x; acc[2 * j + 1] += f.y;
        }
    }
    float* op = out + (size_t)t * HD + c0;
    *(float4*)op       = make_float4(acc[0], acc[1], acc[2], acc[3]);
    *(float4*)(op + 4) = make_float4(acc[4], acc[5], acc[6], acc[7]);
}

// ---------------- launch ----------------
extern "C" void kernel_launch(void* const* d_in, const int* in_sizes, int n_in,
                              void* d_out, int out_size) {
    (void)in_sizes; (void)n_in; (void)out_size;
    const float* x     = (const float*)d_in[0];
    const float* rw    = (const float*)d_in[1];
    const float* gate  = (const float*)d_in[2];
    const float* up    = (const float*)d_in[3];
    const float* down  = (const float*)d_in[4];
    const float* sgate = (const float*)d_in[5];
    const float* sup   = (const float*)d_in[6];
    const float* sdown = (const float*)d_in[7];
    float* out = (float*)d_out;

    cudaFuncSetAttribute(k_gateup, cudaFuncAttributeMaxDynamicSharedMemorySize, GU_SMEM);
    cudaFuncSetAttribute(k_down,   cudaFuncAttributeMaxDynamicSharedMemorySize, DN_SMEM);

    k_pre<<<NT * HD / 2048, 256>>>(x);
    k_router<<<NT, 512>>>(x, rw);
    k_gateup<<<dim3(NT / 128, ID / 64, NE), 256, GU_SMEM>>>(gate, up, sgate, sup);
    k_down  <<<dim3(NT / 128, HD / 128, NE), 256, DN_SMEM>>>(down, sdown);
    k_combine<<<NT, 128>>>(out);
}

// round 13
// speedup vs baseline: 3.1660x; 1.0467x over previous
#include <cuda_runtime.h>
#include <cuda_fp16.h>
#include <math.h>
#include <stdint.h>

// ---------------- problem constants ----------------
constexpr int HD   = 1024;
constexpr int ID   = 512;
constexpr int NEXP = 16;
constexpr int TOPK = 4;
constexpr int NT   = 2048;
constexpr int NE   = 17;          // 16 routed + shared pseudo-expert

// ---------------- device scratch ----------------
__device__ int    g_cnt[NE];
__device__ int    g_tok[NE * NT];
__device__ float  g_rw [NE * NT];
__device__ int    g_pos[NT * TOPK];
__device__ __half g_xh[(size_t)NT * HD];
__device__ __half g_acth[(size_t)NE * NT * ID];   // gathered SwiGLU activations
__device__ __half g_dnh [(size_t)NE * NT * HD];   // per-(expert,slot) down outputs

// ---------------- helpers ----------------
__device__ __forceinline__ uint32_t smem_u32(const void* p) {
    uint32_t a;
    asm("{ .reg .u64 t; cvta.to.shared.u64 t, %1; cvt.u32.u64 %0, t; }" : "=r"(a) : "l"(p));
    return a;
}
__device__ __forceinline__ void cp16(uint32_t dst, const void* src) {
    asm volatile("cp.async.cg.shared.global [%0], [%1], 16;" :: "r"(dst), "l"(src));
}
#define CP_COMMIT() asm volatile("cp.async.commit_group;" ::: "memory")
#define CP_WAIT(n)  asm volatile("cp.async.wait_group %0;" :: "n"(n) : "memory")

#define LDSM4(r, a)                                                              \
    asm volatile("ldmatrix.sync.aligned.m8n8.x4.shared.b16 {%0,%1,%2,%3}, [%4];" \
        : "=r"((r)[0]), "=r"((r)[1]), "=r"((r)[2]), "=r"((r)[3]) : "r"(a))
#define LDSM4T(r, a)                                                             \
    asm volatile("ldmatrix.sync.aligned.m8n8.x4.trans.shared.b16 {%0,%1,%2,%3}, [%4];" \
        : "=r"((r)[0]), "=r"((r)[1]), "=r"((r)[2]), "=r"((r)[3]) : "r"(a))

// mma m16n8k16 f16 -> f32.  C: c0=(g,2tg) c1=(g,2tg+1) c2=(g+8,2tg) c3=(g+8,2tg+1)
__device__ __forceinline__ void mma16(float* c, const uint32_t* a, uint32_t b0, uint32_t b1) {
    asm volatile(
        "mma.sync.aligned.m16n8k16.row.col.f32.f16.f16.f32 "
        "{%0,%1,%2,%3}, {%4,%5,%6,%7}, {%8,%9}, {%0,%1,%2,%3};"
        : "+f"(c[0]), "+f"(c[1]), "+f"(c[2]), "+f"(c[3])
        : "r"(a[0]), "r"(a[1]), "r"(a[2]), "r"(a[3]), "r"(b0), "r"(b1));
}
__device__ __forceinline__ float silu(float g) { return g / (1.f + expf(-g)); }
__device__ __forceinline__ uint2 f4_to_h4(float4 v) {
    __half2 a = __floats2half2_rn(v.x, v.y);
    __half2 b = __floats2half2_rn(v.z, v.w);
    uint2 o;
    o.x = *(uint32_t*)&a; o.y = *(uint32_t*)&b;
    return o;
}

// ---------------- pre: convert x -> fp16, init counters / shared-expert slots ----------------
__global__ void k_pre(const float* __restrict__ x) {
    if (blockIdx.x == 0) {
        for (int j = threadIdx.x; j < NT; j += blockDim.x) {
            g_tok[NEXP * NT + j] = j;
            g_rw [NEXP * NT + j] = 1.0f;
        }
        if (threadIdx.x < NE) g_cnt[threadIdx.x] = (threadIdx.x == NEXP) ? NT : 0;
    }
    int i = (blockIdx.x * blockDim.x + threadIdx.x) * 8;     // grid 1024 * 256 * 8 = 2M
    float4 a = *(const float4*)(x + i);
    float4 b = *(const float4*)(x + i + 4);
    uint2 lo = f4_to_h4(a), hi = f4_to_h4(b);
    uint4 o; o.x = lo.x; o.y = lo.y; o.z = hi.x; o.w = hi.y;
    *(uint4*)(g_xh + i) = o;
}

// ---------------- router: fp32 exact ----------------
__global__ void k_router(const float* __restrict__ x, const float* __restrict__ rw) {
    const int t    = blockIdx.x;
    const int wid  = threadIdx.x >> 5;
    const int lane = threadIdx.x & 31;
    __shared__ float sl[NEXP];

    const float* xr = x + (size_t)t * HD;
    float acc = 0.f;
    for (int h = lane; h < HD; h += 32)
        acc += xr[h] * rw[h * NEXP + wid];
    #pragma unroll
    for (int o = 16; o > 0; o >>= 1)
        acc += __shfl_down_sync(0xffffffffu, acc, o);
    if (lane == 0) sl[wid] = acc;
    __syncthreads();

    if (threadIdx.x == 0) {
        float v[NEXP]; bool used[NEXP];
        #pragma unroll
        for (int e = 0; e < NEXP; e++) { v[e] = 1.f / (1.f + expf(-sl[e])); used[e] = false; }
        #pragma unroll
        for (int k = 0; k < TOPK; k++) {
            int be = -1; float bv = -1.f;
            #pragma unroll
            for (int e = 0; e < NEXP; e++)
                if (!used[e] && v[e] > bv) { bv = v[e]; be = e; }
            used[be] = true;
            int j = atomicAdd(&g_cnt[be], 1);
            g_tok[be * NT + j] = t;
            g_rw [be * NT + j] = bv;
            g_pos[t * TOPK + k] = be * NT + j;
        }
    }
}

// =======================================================================
// gate/up: BM=128, BN=64 (G and U), BK=32, 256 thr / 8 warps (4m x 2n).
// A: fp16 cp.async 3-stage.  B: fp32 LDG -> reg cvt -> STS, 3-buf,
// stsB AFTER the mma block; ONE __syncthreads per stage.
// smem: toks/rws 1KB | A[3][128*40]h | Bg[3][32*72]h | Bu[3][32*72]h
// =======================================================================
constexpr int GU_ASTG = 128 * 40;
constexpr int GU_BSTG = 32 * 72;
constexpr int GU_SMEM = 1024 + (3 * GU_ASTG + 6 * GU_BSTG) * 2;   // 59392 B

__global__ void __launch_bounds__(256, 2)
k_gateup(const float* __restrict__ gate_w, const float* __restrict__ up_w,
         const float* __restrict__ sgate,  const float* __restrict__ sup) {
    const int e    = blockIdx.z;
    const int c    = g_cnt[e];
    const int row0 = blockIdx.x * 128;
    if (row0 >= c) return;
    const int n0   = blockIdx.y * 64;

    extern __shared__ char smc[];
    int*    toks = (int*)smc;
    float*  rws  = (float*)(smc + 512);
    __half* sA   = (__half*)(smc + 1024);
    __half* sG   = sA + 3 * GU_ASTG;
    __half* sU   = sG + 3 * GU_BSTG;
    const int tid = threadIdx.x;

    const float* Wg = (e == NEXP) ? sgate : gate_w + (size_t)e * HD * ID;
    const float* Wu = (e == NEXP) ? sup   : up_w   + (size_t)e * HD * ID;

    if (tid < 128) {
        int r = row0 + tid;
        if (r < c) { toks[tid] = g_tok[e * NT + r]; rws[tid] = g_rw[e * NT + r]; }
        else       { toks[tid] = 0;                 rws[tid] = 0.f; }
    }
    __syncthreads();

    const uint32_t abA = smem_u32(sA);

    auto ldA = [&](int buf, int kk) {
        uint32_t dA = abA + buf * GU_ASTG * 2;
        #pragma unroll
        for (int i = 0; i < 2; i++) {                 // A: 128 x 32h = 512 16B chunks
            int lin = tid + i * 256;
            int r = lin >> 2, q = lin & 3;
            cp16(dA + (r * 40 + q * 8) * 2, g_xh + (size_t)toks[r] * HD + kk + q * 8);
        }
    };

    float4 wg4[2], wu4[2];                            // B prefetch registers
    auto ldgB = [&](int kk) {
        #pragma unroll
        for (int i = 0; i < 2; i++) {                 // 512 float4 over 256 threads
            int lin = tid + i * 256;
            int k = lin >> 4, n4 = lin & 15;
            wg4[i] = *(const float4*)(Wg + (size_t)(kk + k) * ID + n0 + n4 * 4);
            wu4[i] = *(const float4*)(Wu + (size_t)(kk + k) * ID + n0 + n4 * 4);
        }
    };
    auto stsB = [&](int buf) {
        #pragma unroll
        for (int i = 0; i < 2; i++) {
            int lin = tid + i * 256;
            int k = lin >> 4, n4 = lin & 15;
            *(uint2*)(sG + buf * GU_BSTG + k * 72 + n4 * 4) = f4_to_h4(wg4[i]);
            *(uint2*)(sU + buf * GU_BSTG + k * 72 + n4 * 4) = f4_to_h4(wu4[i]);
        }
    };

    const int wid = tid >> 5, lane = tid & 31;
    const int gid = lane >> 2, tg = lane & 3;
    const int wm = wid & 3, wn = wid >> 2;            // 4m x 2n
    const int l15 = lane & 15, l16 = lane >> 4;
    const uint32_t abG = smem_u32(sG), abU = smem_u32(sU);

    float accG[2][4][4] = {}, accU[2][4][4] = {};

    // prologue: A stages 0,1 in flight; B stage 0 in smem, stage 1 in regs
    ldA(0, 0);  CP_COMMIT();
    ldA(1, 32); CP_COMMIT();
    ldgB(0);    stsB(0);
    ldgB(32);

    const int S = HD / 32;   // 32 stages
    for (int s = 0; s < S; s++) {
        if (s + 1 < S) { CP_WAIT(1); } else { CP_WAIT(0); }
        __syncthreads();                               // single sync per stage
        if (s + 2 < S) ldA((s + 2) % 3, (s + 2) * 32);
        CP_COMMIT();

        uint32_t bA = abA + (s % 3) * GU_ASTG * 2;
        uint32_t bG = abG + (s % 3) * GU_BSTG * 2;
        uint32_t bU = abU + (s % 3) * GU_BSTG * 2;

        #pragma unroll
        for (int kq = 0; kq < 2; kq++) {
            uint32_t a[2][4], bg[2][4], bu[2][4];
            #pragma unroll
            for (int mf = 0; mf < 2; mf++)
                LDSM4(a[mf], bA + ((wm * 32 + mf * 16 + l15) * 40 + kq * 16 + l16 * 8) * 2);
            #pragma unroll
            for (int h = 0; h < 2; h++) {
                LDSM4T(bg[h], bG + ((kq * 16 + l15) * 72 + wn * 32 + h * 16 + l16 * 8) * 2);
                LDSM4T(bu[h], bU + ((kq * 16 + l15) * 72 + wn * 32 + h * 16 + l16 * 8) * 2);
            }
            #pragma unroll
            for (int mf = 0; mf < 2; mf++)
                #pragma unroll
                for (int h = 0; h < 2; h++) {
                    mma16(accG[mf][2 * h + 0], a[mf], bg[h][0], bg[h][1]);
                    mma16(accG[mf][2 * h + 1], a[mf], bg[h][2], bg[h][3]);
                    mma16(accU[mf][2 * h + 0], a[mf], bu[h][0], bu[h][1]);
                    mma16(accU[mf][2 * h + 1], a[mf], bu[h][2], bu[h][3]);
                }
        }

        // write NEXT stage's B (regs loaded one stage ago), then fetch the one after
        if (s + 1 < S) stsB((s + 1) % 3);
        if (s + 2 < S) ldgB((s + 2) * 32);
    }

    // epilogue: silu(r*g)*(r*u) -> g_acth (fp16)
    #pragma unroll
    for (int mf = 0; mf < 2; mf++) {
        int rl = wm * 32 + mf * 16 + gid;
        float rr0 = rws[rl], rr1 = rws[rl + 8];
        __half* p0 = g_acth + ((size_t)e * NT + row0 + rl)     * ID + n0 + wn * 32 + 2 * tg;
        __half* p1 = g_acth + ((size_t)e * NT + row0 + rl + 8) * ID + n0 + wn * 32 + 2 * tg;
        #pragma unroll
        for (int nf = 0; nf < 4; nf++) {
            float g0 = rr0 * accG[mf][nf][0], u0 = rr0 * accU[mf][nf][0];
            float g1 = rr0 * accG[mf][nf][1], u1 = rr0 * accU[mf][nf][1];
            float g2 = rr1 * accG[mf][nf][2], u2 = rr1 * accU[mf][nf][2];
            float g3 = rr1 * accG[mf][nf][3], u3 = rr1 * accU[mf][nf][3];
            *(__half2*)(p0 + nf * 8) = __floats2half2_rn(silu(g0) * u0, silu(g1) * u1);
            *(__half2*)(p1 + nf * 8) = __floats2half2_rn(silu(g2) * u2, silu(g3) * u3);
        }
    }
}

// =======================================================================
// down: BM=128, BN=128, BK=32, 256 thr / 8 warps (4m x 2n), warp tile 32x64.
// A: fp16 cp.async 3-stage.  B: fp32 LDG -> reg cvt -> STS, 3-buf,
// stsB AFTER mma; ONE __syncthreads per stage.
// smem: A[3][128*40]h | B[3][32*136]h
// =======================================================================
constexpr int DN_ASTG = 128 * 40;
constexpr int DN_BSTG = 32 * 136;
constexpr int DN_SMEM = (3 * DN_ASTG + 3 * DN_BSTG) * 2;   // 56832 B

__global__ void __launch_bounds__(256, 2)
k_down(const float* __restrict__ down_w, const float* __restrict__ sdown) {
    const int e    = blockIdx.z;
    const int c    = g_cnt[e];
    const int row0 = blockIdx.x * 128;
    if (row0 >= c) return;
    const int n0   = blockIdx.y * 128;

    extern __shared__ char smc[];
    __half* sA = (__half*)smc;
    __half* sB = sA + 3 * DN_ASTG;
    const int tid = threadIdx.x;

    const float* Wd = (e == NEXP) ? sdown : down_w + (size_t)e * ID * HD;
    const __half* Ab = g_acth + ((size_t)e * NT + row0) * ID;

    const uint32_t abA = smem_u32(sA), abB = smem_u32(sB);

    auto ldA = [&](int buf, int kk) {
        uint32_t dA = abA + buf * DN_ASTG * 2;
        #pragma unroll
        for (int i = 0; i < 2; i++) {                 // A: 128 x 32h
            int lin = tid + i * 256;
            int r = lin >> 2, q = lin & 3;
            cp16(dA + (r * 40 + q * 8) * 2, Ab + (size_t)r * ID + kk + q * 8);
        }
    };

    float4 wd4[4];                                    // B prefetch: 1024 float4 / 256 thr
    auto ldgB = [&](int kk) {
        #pragma unroll
        for (int i = 0; i < 4; i++) {
            int lin = tid + i * 256;
            int k = lin >> 5, n4 = lin & 31;
            wd4[i] = *(const float4*)(Wd + (size_t)(kk + k) * HD + n0 + n4 * 4);
        }
    };
    auto stsB = [&](int buf) {
        #pragma unroll
        for (int i = 0; i < 4; i++) {
            int lin = tid + i * 256;
            int k = lin >> 5, n4 = lin & 31;
            *(uint2*)(sB + buf * DN_BSTG + k * 136 + n4 * 4) = f4_to_h4(wd4[i]);
        }
    };

    const int wid = tid >> 5, lane = tid & 31;
    const int gid = lane >> 2, tg = lane & 3;
    const int wm = wid & 3, wn = wid >> 2;            // 4m x 2n
    const int l15 = lane & 15, l16 = lane >> 4;

    float acc[2][8][4] = {};

    ldA(0, 0);  CP_COMMIT();
    ldA(1, 32); CP_COMMIT();
    ldgB(0);    stsB(0);
    ldgB(32);

    const int S = ID / 32;   // 16 stages
    for (int s = 0; s < S; s++) {
        if (s + 1 < S) { CP_WAIT(1); } else { CP_WAIT(0); }
        __syncthreads();                               // single sync per stage
        if (s + 2 < S) ldA((s + 2) % 3, (s + 2) * 32);
        CP_COMMIT();

        uint32_t bA = abA + (s % 3) * DN_ASTG * 2;
        uint32_t bB = abB + (s % 3) * DN_BSTG * 2;

        #pragma unroll
        for (int kq = 0; kq < 2; kq++) {
            uint32_t a[2][4], b[4][4];
            #pragma unroll
            for (int mf = 0; mf < 2; mf++)
                LDSM4(a[mf], bA + ((wm * 32 + mf * 16 + l15) * 40 + kq * 16 + l16 * 8) * 2);
            #pragma unroll
            for (int h = 0; h < 4; h++)
                LDSM4T(b[h], bB + ((kq * 16 + l15) * 136 + wn * 64 + h * 16 + l16 * 8) * 2);
            #pragma unroll
            for (int mf = 0; mf < 2; mf++)
                #pragma unroll
                for (int h = 0; h < 4; h++) {
                    mma16(acc[mf][2 * h + 0], a[mf], b[h][0], b[h][1]);
                    mma16(acc[mf][2 * h + 1], a[mf], b[h][2], b[h][3]);
                }
        }

        if (s + 1 < S) stsB((s + 1) % 3);
        if (s + 2 < S) ldgB((s + 2) * 32);
    }

    // epilogue -> g_dnh (fp16)
    #pragma unroll
    for (int mf = 0; mf < 2; mf++) {
        int rl = wm * 32 + mf * 16 + gid;
        __half* p0 = g_dnh + ((size_t)e * NT + row0 + rl)     * HD + n0 + wn * 64 + 2 * tg;
        __half* p1 = g_dnh + ((size_t)e * NT + row0 + rl + 8) * HD + n0 + wn * 64 + 2 * tg;
        #pragma unroll
        for (int nf = 0; nf < 8; nf++) {
            *(__half2*)(p0 + nf * 8) = __floats2half2_rn(acc[mf][nf][0], acc[mf][nf][1]);
            *(__half2*)(p1 + nf * 8) = __floats2half2_rn(acc[mf][nf][2], acc[mf][nf][3]);
        }
    }
}

// ---------------- combine: out[t] = shared row + 4 routed rows (fp32) ----------------
__global__ void k_combine(float* __restrict__ out) {
    int t  = blockIdx.x;
    int c0 = threadIdx.x * 8;                         // 128 threads x 8 cols
    float acc[8];
    {
        const uint4 v = *(const uint4*)(g_dnh + ((size_t)NEXP * NT + t) * HD + c0);
        const __half2* h = (const __half2*)&v;
        #pragma unroll
        for (int j = 0; j < 4; j++) {
            float2 f = __half22float2(h[j]);
            acc[2 * j] = f.x; acc[2 * j + 1] = f.y;
        }
    }
    #pragma unroll
    for (int k = 0; k < TOPK; k++) {
        const uint4 v = *(const uint4*)(g_dnh + (size_t)g_pos[t * TOPK + k] * HD + c0);
        const __half2* h = (const __half2*)&v;
        #pragma unroll
        for (int j = 0; j < 4; j++) {
            float2 f = __half22float2(h[j]);
            acc[2 * j] += f.x; acc[2 * j + 1] += f.y;
        }
    }
    float* op = out + (size_t)t * HD + c0;
    *(float4*)op       = make_float4(acc[0], acc[1], acc[2], acc[3]);
    *(float4*)(op + 4) = make_float4(acc[4], acc[5], acc[6], acc[7]);
}

// ---------------- launch ----------------
extern "C" void kernel_launch(void* const* d_in, const int* in_sizes, int n_in,
                              void* d_out, int out_size) {
    (void)in_sizes; (void)n_in; (void)out_size;
    const float* x     = (const float*)d_in[0];
    const float* rw    = (const float*)d_in[1];
    const float* gate  = (const float*)d_in[2];
    const float* up    = (const float*)d_in[3];
    const float* down  = (const float*)d_in[4];
    const float* sgate = (const float*)d_in[5];
    const float* sup   = (const float*)d_in[6];
    const float* sdown = (const float*)d_in[7];
    float* out = (float*)d_out;

    cudaFuncSetAttribute(k_gateup, cudaFuncAttributeMaxDynamicSharedMemorySize, GU_SMEM);
    cudaFuncSetAttribute(k_down,   cudaFuncAttributeMaxDynamicSharedMemorySize, DN_SMEM);

    k_pre<<<NT * HD / 2048, 256>>>(x);
    k_router<<<NT, 512>>>(x, rw);
    k_gateup<<<dim3(NT / 128, ID / 64, NE), 256, GU_SMEM>>>(gate, up, sgate, sup);
    k_down  <<<dim3(NT / 128, HD / 128, NE), 256, DN_SMEM>>>(down, sdown);
    k_combine<<<NT, 128>>>(out);
}

// round 15
// speedup vs baseline: 3.1664x; 1.0001x over previous
#include <cuda_runtime.h>
#include <cuda_fp16.h>
#include <math.h>
#include <stdint.h>

// ---------------- problem constants ----------------
constexpr int HD   = 1024;
constexpr int ID   = 512;
constexpr int NEXP = 16;
constexpr int TOPK = 4;
constexpr int NT   = 2048;
constexpr int NE   = 17;          // 16 routed + shared pseudo-expert

// ---------------- device scratch ----------------
__device__ int    g_cnt[NE];
__device__ int    g_tok[NE * NT];
__device__ float  g_rw [NE * NT];
__device__ int    g_pos[NT * TOPK];
__device__ __half g_xh[(size_t)NT * HD];
__device__ __half g_acth[(size_t)NE * NT * ID];   // gathered SwiGLU activations
__device__ __half g_dnh [(size_t)NE * NT * HD];   // per-(expert,slot) down outputs

// ---------------- helpers ----------------
__device__ __forceinline__ uint32_t smem_u32(const void* p) {
    uint32_t a;
    asm("{ .reg .u64 t; cvta.to.shared.u64 t, %1; cvt.u32.u64 %0, t; }" : "=r"(a) : "l"(p));
    return a;
}
__device__ __forceinline__ void cp16(uint32_t dst, const void* src) {
    asm volatile("cp.async.cg.shared.global [%0], [%1], 16;" :: "r"(dst), "l"(src));
}
#define CP_COMMIT() asm volatile("cp.async.commit_group;" ::: "memory")
#define CP_WAIT(n)  asm volatile("cp.async.wait_group %0;" :: "n"(n) : "memory")

#define LDSM4(r, a)                                                              \
    asm volatile("ldmatrix.sync.aligned.m8n8.x4.shared.b16 {%0,%1,%2,%3}, [%4];" \
        : "=r"((r)[0]), "=r"((r)[1]), "=r"((r)[2]), "=r"((r)[3]) : "r"(a))
#define LDSM4T(r, a)                                                             \
    asm volatile("ldmatrix.sync.aligned.m8n8.x4.trans.shared.b16 {%0,%1,%2,%3}, [%4];" \
        : "=r"((r)[0]), "=r"((r)[1]), "=r"((r)[2]), "=r"((r)[3]) : "r"(a))

// mma m16n8k16 f16 -> f32.  C: c0=(g,2tg) c1=(g,2tg+1) c2=(g+8,2tg) c3=(g+8,2tg+1)
__device__ __forceinline__ void mma16(float* c, const uint32_t* a, uint32_t b0, uint32_t b1) {
    asm volatile(
        "mma.sync.aligned.m16n8k16.row.col.f32.f16.f16.f32 "
        "{%0,%1,%2,%3}, {%4,%5,%6,%7}, {%8,%9}, {%0,%1,%2,%3};"
        : "+f"(c[0]), "+f"(c[1]), "+f"(c[2]), "+f"(c[3])
        : "r"(a[0]), "r"(a[1]), "r"(a[2]), "r"(a[3]), "r"(b0), "r"(b1));
}
__device__ __forceinline__ float silu(float g) { return g / (1.f + expf(-g)); }
__device__ __forceinline__ uint2 f4_to_h4(float4 v) {
    __half2 a = __floats2half2_rn(v.x, v.y);
    __half2 b = __floats2half2_rn(v.z, v.w);
    uint2 o;
    o.x = *(uint32_t*)&a; o.y = *(uint32_t*)&b;
    return o;
}

// ---------------- init: reset counters (tiny; must precede k_prep atomics) ----------------
__global__ void k_init() {
    if (threadIdx.x < NE) g_cnt[threadIdx.x] = (threadIdx.x == NEXP) ? NT : 0;
}

// ---------------- prep: one block per token. Stage x row in smem once:
//  - write fp16 copy to g_xh
//  - router logits (8 warps x 2 experts, lane-strided sum == old order bitwise)
//  - top-4 scatter + shared-expert slot ----------------
__global__ void __launch_bounds__(256)
k_prep(const float* __restrict__ x, const float* __restrict__ rw) {
    const int t   = blockIdx.x;
    const int tid = threadIdx.x;
    __shared__ float xs[HD];
    __shared__ float sl[NEXP];

    // load row (4 floats/thread), stage to smem, store fp16 copy
    {
        float4 v = *(const float4*)(x + (size_t)t * HD + tid * 4);
        *(float4*)(xs + tid * 4) = v;
        __half2 h0 = __floats2half2_rn(v.x, v.y);
        __half2 h1 = __floats2half2_rn(v.z, v.w);
        uint2 o; o.x = *(uint32_t*)&h0; o.y = *(uint32_t*)&h1;
        *(uint2*)(g_xh + (size_t)t * HD + tid * 4) = o;
    }
    // shared-expert slot for this token
    if (tid == 0) { g_tok[NEXP * NT + t] = t; g_rw[NEXP * NT + t] = 1.0f; }
    __syncthreads();

    // router: warp w handles experts w and w+8; same strided order as before
    const int w    = tid >> 5;
    const int lane = tid & 31;
    #pragma unroll
    for (int half = 0; half < 2; half++) {
        int e = w + half * 8;
        float acc = 0.f;
        for (int h = lane; h < HD; h += 32)
            acc += xs[h] * rw[h * NEXP + e];
        #pragma unroll
        for (int o = 16; o > 0; o >>= 1)
            acc += __shfl_down_sync(0xffffffffu, acc, o);
        if (lane == 0) sl[e] = acc;
    }
    __syncthreads();

    if (tid == 0) {
        float v[NEXP]; bool used[NEXP];
        #pragma unroll
        for (int e = 0; e < NEXP; e++) { v[e] = 1.f / (1.f + expf(-sl[e])); used[e] = false; }
        #pragma unroll
        for (int k = 0; k < TOPK; k++) {
            int be = -1; float bv = -1.f;
            #pragma unroll
            for (int e = 0; e < NEXP; e++)
                if (!used[e] && v[e] > bv) { bv = v[e]; be = e; }
            used[be] = true;
            int j = atomicAdd(&g_cnt[be], 1);
            g_tok[be * NT + j] = t;
            g_rw [be * NT + j] = bv;
            g_pos[t * TOPK + k] = be * NT + j;
        }
    }
}

// =======================================================================
// gate/up: BM=128, BN=64 (G and U), BK=32, 256 thr / 8 warps (4m x 2n).
// A: fp16 cp.async 3-stage.  B: fp32 LDG -> reg cvt -> STS, 3-buf,
// stsB AFTER the mma block; ONE __syncthreads per stage.
// smem: toks/rws 1KB | A[3][128*40]h | Bg[3][32*72]h | Bu[3][32*72]h
// =======================================================================
constexpr int GU_ASTG = 128 * 40;
constexpr int GU_BSTG = 32 * 72;
constexpr int GU_SMEM = 1024 + (3 * GU_ASTG + 6 * GU_BSTG) * 2;   // 59392 B

__global__ void __launch_bounds__(256, 2)
k_gateup(const float* __restrict__ gate_w, const float* __restrict__ up_w,
         const float* __restrict__ sgate,  const float* __restrict__ sup) {
    const int e    = blockIdx.z;
    const int c    = g_cnt[e];
    const int row0 = blockIdx.x * 128;
    if (row0 >= c) return;
    const int n0   = blockIdx.y * 64;

    extern __shared__ char smc[];
    int*    toks = (int*)smc;
    float*  rws  = (float*)(smc + 512);
    __half* sA   = (__half*)(smc + 1024);
    __half* sG   = sA + 3 * GU_ASTG;
    __half* sU   = sG + 3 * GU_BSTG;
    const int tid = threadIdx.x;

    const float* Wg = (e == NEXP) ? sgate : gate_w + (size_t)e * HD * ID;
    const float* Wu = (e == NEXP) ? sup   : up_w   + (size_t)e * HD * ID;

    if (tid < 128) {
        int r = row0 + tid;
        if (r < c) { toks[tid] = g_tok[e * NT + r]; rws[tid] = g_rw[e * NT + r]; }
        else       { toks[tid] = 0;                 rws[tid] = 0.f; }
    }
    __syncthreads();

    const uint32_t abA = smem_u32(sA);

    auto ldA = [&](int buf, int kk) {
        uint32_t dA = abA + buf * GU_ASTG * 2;
        #pragma unroll
        for (int i = 0; i < 2; i++) {                 // A: 128 x 32h = 512 16B chunks
            int lin = tid + i * 256;
            int r = lin >> 2, q = lin & 3;
            cp16(dA + (r * 40 + q * 8) * 2, g_xh + (size_t)toks[r] * HD + kk + q * 8);
        }
    };

    float4 wg4[2], wu4[2];                            // B prefetch registers
    auto ldgB = [&](int kk) {
        #pragma unroll
        for (int i = 0; i < 2; i++) {                 // 512 float4 over 256 threads
            int lin = tid + i * 256;
            int k = lin >> 4, n4 = lin & 15;
            wg4[i] = *(const float4*)(Wg + (size_t)(kk + k) * ID + n0 + n4 * 4);
            wu4[i] = *(const float4*)(Wu + (size_t)(kk + k) * ID + n0 + n4 * 4);
        }
    };
    auto stsB = [&](int buf) {
        #pragma unroll
        for (int i = 0; i < 2; i++) {
            int lin = tid + i * 256;
            int k = lin >> 4, n4 = lin & 15;
            *(uint2*)(sG + buf * GU_BSTG + k * 72 + n4 * 4) = f4_to_h4(wg4[i]);
            *(uint2*)(sU + buf * GU_BSTG + k * 72 + n4 * 4) = f4_to_h4(wu4[i]);
        }
    };

    const int wid = tid >> 5, lane = tid & 31;
    const int gid = lane >> 2, tg = lane & 3;
    const int wm = wid & 3, wn = wid >> 2;            // 4m x 2n
    const int l15 = lane & 15, l16 = lane >> 4;
    const uint32_t abG = smem_u32(sG), abU = smem_u32(sU);

    float accG[2][4][4] = {}, accU[2][4][4] = {};

    // prologue: A stages 0,1 in flight; B stage 0 in smem, stage 1 in regs
    ldA(0, 0);  CP_COMMIT();
    ldA(1, 32); CP_COMMIT();
    ldgB(0);    stsB(0);
    ldgB(32);

    const int S = HD / 32;   // 32 stages
    for (int s = 0; s < S; s++) {
        if (s + 1 < S) { CP_WAIT(1); } else { CP_WAIT(0); }
        __syncthreads();                               // single sync per stage
        if (s + 2 < S) ldA((s + 2) % 3, (s + 2) * 32);
        CP_COMMIT();

        uint32_t bA = abA + (s % 3) * GU_ASTG * 2;
        uint32_t bG = abG + (s % 3) * GU_BSTG * 2;
        uint32_t bU = abU + (s % 3) * GU_BSTG * 2;

        #pragma unroll
        for (int kq = 0; kq < 2; kq++) {
            uint32_t a[2][4], bg[2][4], bu[2][4];
            #pragma unroll
            for (int mf = 0; mf < 2; mf++)
                LDSM4(a[mf], bA + ((wm * 32 + mf * 16 + l15) * 40 + kq * 16 + l16 * 8) * 2);
            #pragma unroll
            for (int h = 0; h < 2; h++) {
                LDSM4T(bg[h], bG + ((kq * 16 + l15) * 72 + wn * 32 + h * 16 + l16 * 8) * 2);
                LDSM4T(bu[h], bU + ((kq * 16 + l15) * 72 + wn * 32 + h * 16 + l16 * 8) * 2);
            }
            #pragma unroll
            for (int mf = 0; mf < 2; mf++)
                #pragma unroll
                for (int h = 0; h < 2; h++) {
                    mma16(accG[mf][2 * h + 0], a[mf], bg[h][0], bg[h][1]);
                    mma16(accG[mf][2 * h + 1], a[mf], bg[h][2], bg[h][3]);
                    mma16(accU[mf][2 * h + 0], a[mf], bu[h][0], bu[h][1]);
                    mma16(accU[mf][2 * h + 1], a[mf], bu[h][2], bu[h][3]);
                }
        }

        // write NEXT stage's B (regs loaded one stage ago), then fetch the one after
        if (s + 1 < S) stsB((s + 1) % 3);
        if (s + 2 < S) ldgB((s + 2) * 32);
    }

    // epilogue: silu(r*g)*(r*u) -> g_acth (fp16)
    #pragma unroll
    for (int mf = 0; mf < 2; mf++) {
        int rl = wm * 32 + mf * 16 + gid;
        float rr0 = rws[rl], rr1 = rws[rl + 8];
        __half* p0 = g_acth + ((size_t)e * NT + row0 + rl)     * ID + n0 + wn * 32 + 2 * tg;
        __half* p1 = g_acth + ((size_t)e * NT + row0 + rl + 8) * ID + n0 + wn * 32 + 2 * tg;
        #pragma unroll
        for (int nf = 0; nf < 4; nf++) {
            float g0 = rr0 * accG[mf][nf][0], u0 = rr0 * accU[mf][nf][0];
            float g1 = rr0 * accG[mf][nf][1], u1 = rr0 * accU[mf][nf][1];
            float g2 = rr1 * accG[mf][nf][2], u2 = rr1 * accU[mf][nf][2];
            float g3 = rr1 * accG[mf][nf][3], u3 = rr1 * accU[mf][nf][3];
            *(__half2*)(p0 + nf * 8) = __floats2half2_rn(silu(g0) * u0, silu(g1) * u1);
            *(__half2*)(p1 + nf * 8) = __floats2half2_rn(silu(g2) * u2, silu(g3) * u3);
        }
    }
}

// =======================================================================
// down: BM=128, BN=128, BK=32, 256 thr / 8 warps (4m x 2n), warp tile 32x64.
// A: fp16 cp.async 3-stage.  B: fp32 LDG -> reg cvt -> STS, 3-buf,
// stsB AFTER mma; ONE __syncthreads per stage.
// smem: A[3][128*40]h | B[3][32*136]h
// =======================================================================
constexpr int DN_ASTG = 128 * 40;
constexpr int DN_BSTG = 32 * 136;
constexpr int DN_SMEM = (3 * DN_ASTG + 3 * DN_BSTG) * 2;   // 56832 B

__global__ void __launch_bounds__(256, 2)
k_down(const float* __restrict__ down_w, const float* __restrict__ sdown) {
    const int e    = blockIdx.z;
    const int c    = g_cnt[e];
    const int row0 = blockIdx.x * 128;
    if (row0 >= c) return;
    const int n0   = blockIdx.y * 128;

    extern __shared__ char smc[];
    __half* sA = (__half*)smc;
    __half* sB = sA + 3 * DN_ASTG;
    const int tid = threadIdx.x;

    const float* Wd = (e == NEXP) ? sdown : down_w + (size_t)e * ID * HD;
    const __half* Ab = g_acth + ((size_t)e * NT + row0) * ID;

    const uint32_t abA = smem_u32(sA), abB = smem_u32(sB);

    auto ldA = [&](int buf, int kk) {
        uint32_t dA = abA + buf * DN_ASTG * 2;
        #pragma unroll
        for (int i = 0; i < 2; i++) {                 // A: 128 x 32h
            int lin = tid + i * 256;
            int r = lin >> 2, q = lin & 3;
            cp16(dA + (r * 40 + q * 8) * 2, Ab + (size_t)r * ID + kk + q * 8);
        }
    };

    float4 wd4[4];                                    // B prefetch: 1024 float4 / 256 thr
    auto ldgB = [&](int kk) {
        #pragma unroll
        for (int i = 0; i < 4; i++) {
            int lin = tid + i * 256;
            int k = lin >> 5, n4 = lin & 31;
            wd4[i] = *(const float4*)(Wd + (size_t)(kk + k) * HD + n0 + n4 * 4);
        }
    };
    auto stsB = [&](int buf) {
        #pragma unroll
        for (int i = 0; i < 4; i++) {
            int lin = tid + i * 256;
            int k = lin >> 5, n4 = lin & 31;
            *(uint2*)(sB + buf * DN_BSTG + k * 136 + n4 * 4) = f4_to_h4(wd4[i]);
        }
    };

    const int wid = tid >> 5, lane = tid & 31;
    const int gid = lane >> 2, tg = lane & 3;
    const int wm = wid & 3, wn = wid >> 2;            // 4m x 2n
    const int l15 = lane & 15, l16 = lane >> 4;

    float acc[2][8][4] = {};

    ldA(0, 0);  CP_COMMIT();
    ldA(1, 32); CP_COMMIT();
    ldgB(0);    stsB(0);
    ldgB(32);

    const int S = ID / 32;   // 16 stages
    for (int s = 0; s < S; s++) {
        if (s + 1 < S) { CP_WAIT(1); } else { CP_WAIT(0); }
        __syncthreads();                               // single sync per stage
        if (s + 2 < S) ldA((s + 2) % 3, (s + 2) * 32);
        CP_COMMIT();

        uint32_t bA = abA + (s % 3) * DN_ASTG * 2;
        uint32_t bB = abB + (s % 3) * DN_BSTG * 2;

        #pragma unroll
        for (int kq = 0; kq < 2; kq++) {
            uint32_t a[2][4], b[4][4];
            #pragma unroll
            for (int mf = 0; mf < 2; mf++)
                LDSM4(a[mf], bA + ((wm * 32 + mf * 16 + l15) * 40 + kq * 16 + l16 * 8) * 2);
            #pragma unroll
            for (int h = 0; h < 4; h++)
                LDSM4T(b[h], bB + ((kq * 16 + l15) * 136 + wn * 64 + h * 16 + l16 * 8) * 2);
            #pragma unroll
            for (int mf = 0; mf < 2; mf++)
                #pragma unroll
                for (int h = 0; h < 4; h++) {
                    mma16(acc[mf][2 * h + 0], a[mf], b[h][0], b[h][1]);
                    mma16(acc[mf][2 * h + 1], a[mf], b[h][2], b[h][3]);
                }
        }

        if (s + 1 < S) stsB((s + 1) % 3);
        if (s + 2 < S) ldgB((s + 2) * 32);
    }

    // epilogue -> g_dnh (fp16)
    #pragma unroll
    for (int mf = 0; mf < 2; mf++) {
        int rl = wm * 32 + mf * 16 + gid;
        __half* p0 = g_dnh + ((size_t)e * NT + row0 + rl)     * HD + n0 + wn * 64 + 2 * tg;
        __half* p1 = g_dnh + ((size_t)e * NT + row0 + rl + 8) * HD + n0 + wn * 64 + 2 * tg;
        #pragma unroll
        for (int nf = 0; nf < 8; nf++) {
            *(__half2*)(p0 + nf * 8) = __floats2half2_rn(acc[mf][nf][0], acc[mf][nf][1]);
            *(__half2*)(p1 + nf * 8) = __floats2half2_rn(acc[mf][nf][2], acc[mf][nf][3]);
        }
    }
}

// ---------------- combine: out[t] = shared row + 4 routed rows (fp32) ----------------
__global__ void k_combine(float* __restrict__ out) {
    int t  = blockIdx.x;
    int c0 = threadIdx.x * 8;                         // 128 threads x 8 cols
    float acc[8];
    {
        const uint4 v = *(const uint4*)(g_dnh + ((size_t)NEXP * NT + t) * HD + c0);
        const __half2* h = (const __half2*)&v;
        #pragma unroll
        for (int j = 0; j < 4; j++) {
            float2 f = __half22float2(h[j]);
            acc[2 * j] = f.x; acc[2 * j + 1] = f.y;
        }
    }
    #pragma unroll
    for (int k = 0; k < TOPK; k++) {
        const uint4 v = *(const uint4*)(g_dnh + (size_t)g_pos[t * TOPK + k] * HD + c0);
        const __half2* h = (const __half2*)&v;
        #pragma unroll
        for (int j = 0; j < 4; j++) {
            float2 f = __half22float2(h[j]);
            acc[2 * j] += f.x; acc[2 * j + 1] += f.y;
        }
    }
    float* op = out + (size_t)t * HD + c0;
    *(float4*)op       = make_float4(acc[0], acc[1], acc[2], acc[3]);
    *(float4*)(op + 4) = make_float4(acc[4], acc[5], acc[6], acc[7]);
}

// ---------------- launch ----------------
extern "C" void kernel_launch(void* const* d_in, const int* in_sizes, int n_in,
                              void* d_out, int out_size) {
    (void)in_sizes; (void)n_in; (void)out_size;
    const float* x     = (const float*)d_in[0];
    const float* rw    = (const float*)d_in[1];
    const float* gate  = (const float*)d_in[2];
    const float* up    = (const float*)d_in[3];
    const float* down  = (const float*)d_in[4];
    const float* sgate = (const float*)d_in[5];
    const float* sup   = (const float*)d_in[6];
    const float* sdown = (const float*)d_in[7];
    float* out = (float*)d_out;

    cudaFuncSetAttribute(k_gateup, cudaFuncAttributeMaxDynamicSharedMemorySize, GU_SMEM);
    cudaFuncSetAttribute(k_down,   cudaFuncAttributeMaxDynamicSharedMemorySize, DN_SMEM);

    k_init<<<1, 32>>>();
    k_prep<<<NT, 256>>>(x, rw);
    k_gateup<<<dim3(NT / 128, ID / 64, NE), 256, GU_SMEM>>>(gate, up, sgate, sup);
    k_down  <<<dim3(NT / 128, HD / 128, NE), 256, DN_SMEM>>>(down, sdown);
    k_combine<<<NT, 128>>>(out);
}

// round 16
// speedup vs baseline: 3.2511x; 1.0267x over previous
#include <cuda_runtime.h>
#include <cuda_fp16.h>
#include <math.h>
#include <stdint.h>

// ---------------- problem constants ----------------
constexpr int HD   = 1024;
constexpr int ID   = 512;
constexpr int NEXP = 16;
constexpr int TOPK = 4;
constexpr int NT   = 2048;
constexpr int NE   = 17;          // 16 routed + shared pseudo-expert

// ---------------- device scratch ----------------
__device__ int    g_cnt[NE];
__device__ int    g_tok[NE * NT];
__device__ float  g_rw [NE * NT];
__device__ int    g_pos[NT * TOPK];
__device__ __half g_xh[(size_t)NT * HD];
__device__ __half g_acth[(size_t)NE * NT * ID];   // gathered SwiGLU activations
__device__ __half g_dnh [(size_t)NE * NT * HD];   // per-(expert,slot) down outputs

// ---------------- helpers ----------------
__device__ __forceinline__ uint32_t smem_u32(const void* p) {
    uint32_t a;
    asm("{ .reg .u64 t; cvta.to.shared.u64 t, %1; cvt.u32.u64 %0, t; }" : "=r"(a) : "l"(p));
    return a;
}
__device__ __forceinline__ void cp16(uint32_t dst, const void* src) {
    asm volatile("cp.async.cg.shared.global [%0], [%1], 16;" :: "r"(dst), "l"(src));
}
#define CP_COMMIT() asm volatile("cp.async.commit_group;" ::: "memory")
#define CP_WAIT(n)  asm volatile("cp.async.wait_group %0;" :: "n"(n) : "memory")

#define LDSM4(r, a)                                                              \
    asm volatile("ldmatrix.sync.aligned.m8n8.x4.shared.b16 {%0,%1,%2,%3}, [%4];" \
        : "=r"((r)[0]), "=r"((r)[1]), "=r"((r)[2]), "=r"((r)[3]) : "r"(a))
#define LDSM4T(r, a)                                                             \
    asm volatile("ldmatrix.sync.aligned.m8n8.x4.trans.shared.b16 {%0,%1,%2,%3}, [%4];" \
        : "=r"((r)[0]), "=r"((r)[1]), "=r"((r)[2]), "=r"((r)[3]) : "r"(a))

// mma m16n8k16 f16 -> f32.  C: c0=(g,2tg) c1=(g,2tg+1) c2=(g+8,2tg) c3=(g+8,2tg+1)
__device__ __forceinline__ void mma16(float* c, const uint32_t* a, uint32_t b0, uint32_t b1) {
    asm volatile(
        "mma.sync.aligned.m16n8k16.row.col.f32.f16.f16.f32 "
        "{%0,%1,%2,%3}, {%4,%5,%6,%7}, {%8,%9}, {%0,%1,%2,%3};"
        : "+f"(c[0]), "+f"(c[1]), "+f"(c[2]), "+f"(c[3])
        : "r"(a[0]), "r"(a[1]), "r"(a[2]), "r"(a[3]), "r"(b0), "r"(b1));
}
// silu via single-MUFU tanh.approx: silu(g) = 0.5*g*(1 + tanh(g/2))
__device__ __forceinline__ float silu(float g) {
    float t;
    asm("tanh.approx.f32 %0, %1;" : "=f"(t) : "f"(0.5f * g));
    return 0.5f * g * (1.f + t);
}
__device__ __forceinline__ uint2 f4_to_h4(float4 v) {
    __half2 a = __floats2half2_rn(v.x, v.y);
    __half2 b = __floats2half2_rn(v.z, v.w);
    uint2 o;
    o.x = *(uint32_t*)&a; o.y = *(uint32_t*)&b;
    return o;
}

// ---------------- init: reset counters (tiny; must precede k_prep atomics) ----------------
__global__ void k_init() {
    if (threadIdx.x < NE) g_cnt[threadIdx.x] = (threadIdx.x == NEXP) ? NT : 0;
}

// ---------------- prep: one block per token. Stage x row in smem once:
//  - write fp16 copy to g_xh
//  - router logits (8 warps x 2 experts, lane-strided sum == old order bitwise)
//  - top-4 scatter + shared-expert slot ----------------
__global__ void __launch_bounds__(256)
k_prep(const float* __restrict__ x, const float* __restrict__ rw) {
    const int t   = blockIdx.x;
    const int tid = threadIdx.x;
    __shared__ float xs[HD];
    __shared__ float sl[NEXP];

    // load row (4 floats/thread), stage to smem, store fp16 copy
    {
        float4 v = *(const float4*)(x + (size_t)t * HD + tid * 4);
        *(float4*)(xs + tid * 4) = v;
        __half2 h0 = __floats2half2_rn(v.x, v.y);
        __half2 h1 = __floats2half2_rn(v.z, v.w);
        uint2 o; o.x = *(uint32_t*)&h0; o.y = *(uint32_t*)&h1;
        *(uint2*)(g_xh + (size_t)t * HD + tid * 4) = o;
    }
    // shared-expert slot for this token
    if (tid == 0) { g_tok[NEXP * NT + t] = t; g_rw[NEXP * NT + t] = 1.0f; }
    __syncthreads();

    // router: warp w handles experts w and w+8; same strided order as before
    const int w    = tid >> 5;
    const int lane = tid & 31;
    #pragma unroll
    for (int half = 0; half < 2; half++) {
        int e = w + half * 8;
        float acc = 0.f;
        for (int h = lane; h < HD; h += 32)
            acc += xs[h] * rw[h * NEXP + e];
        #pragma unroll
        for (int o = 16; o > 0; o >>= 1)
            acc += __shfl_down_sync(0xffffffffu, acc, o);
        if (lane == 0) sl[e] = acc;
    }
    __syncthreads();

    if (tid == 0) {
        float v[NEXP]; bool used[NEXP];
        #pragma unroll
        for (int e = 0; e < NEXP; e++) { v[e] = 1.f / (1.f + expf(-sl[e])); used[e] = false; }
        #pragma unroll
        for (int k = 0; k < TOPK; k++) {
            int be = -1; float bv = -1.f;
            #pragma unroll
            for (int e = 0; e < NEXP; e++)
                if (!used[e] && v[e] > bv) { bv = v[e]; be = e; }
            used[be] = true;
            int j = atomicAdd(&g_cnt[be], 1);
            g_tok[be * NT + j] = t;
            g_rw [be * NT + j] = bv;
            g_pos[t * TOPK + k] = be * NT + j;
        }
    }
}

// =======================================================================
// gate/up: BM=128, BN=64 (G and U), BK=32, 256 thr / 8 warps (4m x 2n).
// A: fp16 cp.async 3-stage.  B: fp32 LDG -> reg cvt -> STS, 3-buf,
// stsB AFTER the mma block; ONE __syncthreads per stage.
// smem: toks/rws 1KB | A[3][128*40]h | Bg[3][32*72]h | Bu[3][32*72]h
// =======================================================================
constexpr int GU_ASTG = 128 * 40;
constexpr int GU_BSTG = 32 * 72;
constexpr int GU_SMEM = 1024 + (3 * GU_ASTG + 6 * GU_BSTG) * 2;   // 59392 B

__global__ void __launch_bounds__(256, 2)
k_gateup(const float* __restrict__ gate_w, const float* __restrict__ up_w,
         const float* __restrict__ sgate,  const float* __restrict__ sup) {
    const int e    = blockIdx.z;
    const int c    = g_cnt[e];
    const int row0 = blockIdx.x * 128;
    if (row0 >= c) return;
    const int n0   = blockIdx.y * 64;

    extern __shared__ char smc[];
    int*    toks = (int*)smc;
    float*  rws  = (float*)(smc + 512);
    __half* sA   = (__half*)(smc + 1024);
    __half* sG   = sA + 3 * GU_ASTG;
    __half* sU   = sG + 3 * GU_BSTG;
    const int tid = threadIdx.x;

    const float* Wg = (e == NEXP) ? sgate : gate_w + (size_t)e * HD * ID;
    const float* Wu = (e == NEXP) ? sup   : up_w   + (size_t)e * HD * ID;

    if (tid < 128) {
        int r = row0 + tid;
        if (r < c) { toks[tid] = g_tok[e * NT + r]; rws[tid] = g_rw[e * NT + r]; }
        else       { toks[tid] = 0;                 rws[tid] = 0.f; }
    }
    __syncthreads();

    const uint32_t abA = smem_u32(sA);

    auto ldA = [&](int buf, int kk) {
        uint32_t dA = abA + buf * GU_ASTG * 2;
        #pragma unroll
        for (int i = 0; i < 2; i++) {                 // A: 128 x 32h = 512 16B chunks
            int lin = tid + i * 256;
            int r = lin >> 2, q = lin & 3;
            cp16(dA + (r * 40 + q * 8) * 2, g_xh + (size_t)toks[r] * HD + kk + q * 8);
        }
    };

    float4 wg4[2], wu4[2];                            // B prefetch registers
    auto ldgB = [&](int kk) {
        #pragma unroll
        for (int i = 0; i < 2; i++) {                 // 512 float4 over 256 threads
            int lin = tid + i * 256;
            int k = lin >> 4, n4 = lin & 15;
            wg4[i] = *(const float4*)(Wg + (size_t)(kk + k) * ID + n0 + n4 * 4);
            wu4[i] = *(const float4*)(Wu + (size_t)(kk + k) * ID + n0 + n4 * 4);
        }
    };
    auto stsB = [&](int buf) {
        #pragma unroll
        for (int i = 0; i < 2; i++) {
            int lin = tid + i * 256;
            int k = lin >> 4, n4 = lin & 15;
            *(uint2*)(sG + buf * GU_BSTG + k * 72 + n4 * 4) = f4_to_h4(wg4[i]);
            *(uint2*)(sU + buf * GU_BSTG + k * 72 + n4 * 4) = f4_to_h4(wu4[i]);
        }
    };

    const int wid = tid >> 5, lane = tid & 31;
    const int gid = lane >> 2, tg = lane & 3;
    const int wm = wid & 3, wn = wid >> 2;            // 4m x 2n
    const int l15 = lane & 15, l16 = lane >> 4;
    const uint32_t abG = smem_u32(sG), abU = smem_u32(sU);

    float accG[2][4][4] = {}, accU[2][4][4] = {};

    // prologue: A stages 0,1 in flight; B stage 0 in smem, stage 1 in regs
    ldA(0, 0);  CP_COMMIT();
    ldA(1, 32); CP_COMMIT();
    ldgB(0);    stsB(0);
    ldgB(32);

    const int S = HD / 32;   // 32 stages
    for (int s = 0; s < S; s++) {
        if (s + 1 < S) { CP_WAIT(1); } else { CP_WAIT(0); }
        __syncthreads();                               // single sync per stage
        if (s + 2 < S) ldA((s + 2) % 3, (s + 2) * 32);
        CP_COMMIT();

        uint32_t bA = abA + (s % 3) * GU_ASTG * 2;
        uint32_t bG = abG + (s % 3) * GU_BSTG * 2;
        uint32_t bU = abU + (s % 3) * GU_BSTG * 2;

        #pragma unroll
        for (int kq = 0; kq < 2; kq++) {
            uint32_t a[2][4], bg[2][4], bu[2][4];
            #pragma unroll
            for (int mf = 0; mf < 2; mf++)
                LDSM4(a[mf], bA + ((wm * 32 + mf * 16 + l15) * 40 + kq * 16 + l16 * 8) * 2);
            #pragma unroll
            for (int h = 0; h < 2; h++) {
                LDSM4T(bg[h], bG + ((kq * 16 + l15) * 72 + wn * 32 + h * 16 + l16 * 8) * 2);
                LDSM4T(bu[h], bU + ((kq * 16 + l15) * 72 + wn * 32 + h * 16 + l16 * 8) * 2);
            }
            #pragma unroll
            for (int mf = 0; mf < 2; mf++)
                #pragma unroll
                for (int h = 0; h < 2; h++) {
                    mma16(accG[mf][2 * h + 0], a[mf], bg[h][0], bg[h][1]);
                    mma16(accG[mf][2 * h + 1], a[mf], bg[h][2], bg[h][3]);
                    mma16(accU[mf][2 * h + 0], a[mf], bu[h][0], bu[h][1]);
                    mma16(accU[mf][2 * h + 1], a[mf], bu[h][2], bu[h][3]);
                }
        }

        // write NEXT stage's B (regs loaded one stage ago), then fetch the one after
        if (s + 1 < S) stsB((s + 1) % 3);
        if (s + 2 < S) ldgB((s + 2) * 32);
    }

    // epilogue: silu(r*g)*(r*u) -> g_acth (fp16)
    #pragma unroll
    for (int mf = 0; mf < 2; mf++) {
        int rl = wm * 32 + mf * 16 + gid;
        float rr0 = rws[rl], rr1 = rws[rl + 8];
        __half* p0 = g_acth + ((size_t)e * NT + row0 + rl)     * ID + n0 + wn * 32 + 2 * tg;
        __half* p1 = g_acth + ((size_t)e * NT + row0 + rl + 8) * ID + n0 + wn * 32 + 2 * tg;
        #pragma unroll
        for (int nf = 0; nf < 4; nf++) {
            float g0 = rr0 * accG[mf][nf][0], u0 = rr0 * accU[mf][nf][0];
            float g1 = rr0 * accG[mf][nf][1], u1 = rr0 * accU[mf][nf][1];
            float g2 = rr1 * accG[mf][nf][2], u2 = rr1 * accU[mf][nf][2];
            float g3 = rr1 * accG[mf][nf][3], u3 = rr1 * accU[mf][nf][3];
            *(__half2*)(p0 + nf * 8) = __floats2half2_rn(silu(g0) * u0, silu(g1) * u1);
            *(__half2*)(p1 + nf * 8) = __floats2half2_rn(silu(g2) * u2, silu(g3) * u3);
        }
    }
}

// =======================================================================
// down: BM=128, BN=128, BK=32, 256 thr / 8 warps (4m x 2n), warp tile 32x64.
// A: fp16 cp.async 3-stage.  B: fp32 LDG -> reg cvt -> STS, 3-buf,
// stsB AFTER mma; ONE __syncthreads per stage.
// smem: A[3][128*40]h | B[3][32*136]h
// =======================================================================
constexpr int DN_ASTG = 128 * 40;
constexpr int DN_BSTG = 32 * 136;
constexpr int DN_SMEM = (3 * DN_ASTG + 3 * DN_BSTG) * 2;   // 56832 B

__global__ void __launch_bounds__(256, 2)
k_down(const float* __restrict__ down_w, const float* __restrict__ sdown) {
    const int e    = blockIdx.z;
    const int c    = g_cnt[e];
    const int row0 = blockIdx.x * 128;
    if (row0 >= c) return;
    const int n0   = blockIdx.y * 128;

    extern __shared__ char smc[];
    __half* sA = (__half*)smc;
    __half* sB = sA + 3 * DN_ASTG;
    const int tid = threadIdx.x;

    const float* Wd = (e == NEXP) ? sdown : down_w + (size_t)e * ID * HD;
    const __half* Ab = g_acth + ((size_t)e * NT + row0) * ID;

    const uint32_t abA = smem_u32(sA), abB = smem_u32(sB);

    auto ldA = [&](int buf, int kk) {
        uint32_t dA = abA + buf * DN_ASTG * 2;
        #pragma unroll
        for (int i = 0; i < 2; i++) {                 // A: 128 x 32h
            int lin = tid + i * 256;
            int r = lin >> 2, q = lin & 3;
            cp16(dA + (r * 40 + q * 8) * 2, Ab + (size_t)r * ID + kk + q * 8);
        }
    };

    float4 wd4[4];                                    // B prefetch: 1024 float4 / 256 thr
    auto ldgB = [&](int kk) {
        #pragma unroll
        for (int i = 0; i < 4; i++) {
            int lin = tid + i * 256;
            int k = lin >> 5, n4 = lin & 31;
            wd4[i] = *(const float4*)(Wd + (size_t)(kk + k) * HD + n0 + n4 * 4);
        }
    };
    auto stsB = [&](int buf) {
        #pragma unroll
        for (int i = 0; i < 4; i++) {
            int lin = tid + i * 256;
            int k = lin >> 5, n4 = lin & 31;
            *(uint2*)(sB + buf * DN_BSTG + k * 136 + n4 * 4) = f4_to_h4(wd4[i]);
        }
    };

    const int wid = tid >> 5, lane = tid & 31;
    const int gid = lane >> 2, tg = lane & 3;
    const int wm = wid & 3, wn = wid >> 2;            // 4m x 2n
    const int l15 = lane & 15, l16 = lane >> 4;

    float acc[2][8][4] = {};

    ldA(0, 0);  CP_COMMIT();
    ldA(1, 32); CP_COMMIT();
    ldgB(0);    stsB(0);
    ldgB(32);

    const int S = ID / 32;   // 16 stages
    for (int s = 0; s < S; s++) {
        if (s + 1 < S) { CP_WAIT(1); } else { CP_WAIT(0); }
        __syncthreads();                               // single sync per stage
        if (s + 2 < S) ldA((s + 2) % 3, (s + 2) * 32);
        CP_COMMIT();

        uint32_t bA = abA + (s % 3) * DN_ASTG * 2;
        uint32_t bB = abB + (s % 3) * DN_BSTG * 2;

        #pragma unroll
        for (int kq = 0; kq < 2; kq++) {
            uint32_t a[2][4], b[4][4];
            #pragma unroll
            for (int mf = 0; mf < 2; mf++)
                LDSM4(a[mf], bA + ((wm * 32 + mf * 16 + l15) * 40 + kq * 16 + l16 * 8) * 2);
            #pragma unroll
            for (int h = 0; h < 4; h++)
                LDSM4T(b[h], bB + ((kq * 16 + l15) * 136 + wn * 64 + h * 16 + l16 * 8) * 2);
            #pragma unroll
            for (int mf = 0; mf < 2; mf++)
                #pragma unroll
                for (int h = 0; h < 4; h++) {
                    mma16(acc[mf][2 * h + 0], a[mf], b[h][0], b[h][1]);
                    mma16(acc[mf][2 * h + 1], a[mf], b[h][2], b[h][3]);
                }
        }

        if (s + 1 < S) stsB((s + 1) % 3);
        if (s + 2 < S) ldgB((s + 2) * 32);
    }

    // epilogue -> g_dnh (fp16)
    #pragma unroll
    for (int mf = 0; mf < 2; mf++) {
        int rl = wm * 32 + mf * 16 + gid;
        __half* p0 = g_dnh + ((size_t)e * NT + row0 + rl)     * HD + n0 + wn * 64 + 2 * tg;
        __half* p1 = g_dnh + ((size_t)e * NT + row0 + rl + 8) * HD + n0 + wn * 64 + 2 * tg;
        #pragma unroll
        for (int nf = 0; nf < 8; nf++) {
            *(__half2*)(p0 + nf * 8) = __floats2half2_rn(acc[mf][nf][0], acc[mf][nf][1]);
            *(__half2*)(p1 + nf * 8) = __floats2half2_rn(acc[mf][nf][2], acc[mf][nf][3]);
        }
    }
}

// ---------------- combine: out[t] = shared row + 4 routed rows (fp32) ----------------
__global__ void k_combine(float* __restrict__ out) {
    int t  = blockIdx.x;
    int c0 = threadIdx.x * 8;                         // 128 threads x 8 cols
    float acc[8];
    {
        const uint4 v = *(const uint4*)(g_dnh + ((size_t)NEXP * NT + t) * HD + c0);
        const __half2* h = (const __half2*)&v;
        #pragma unroll
        for (int j = 0; j < 4; j++) {
            float2 f = __half22float2(h[j]);
            acc[2 * j] = f.x; acc[2 * j + 1] = f.y;
        }
    }
    #pragma unroll
    for (int k = 0; k < TOPK; k++) {
        const uint4 v = *(const uint4*)(g_dnh + (size_t)g_pos[t * TOPK + k] * HD + c0);
        const __half2* h = (const __half2*)&v;
        #pragma unroll
        for (int j = 0; j < 4; j++) {
            float2 f = __half22float2(h[j]);
            acc[2 * j] += f.x; acc[2 * j + 1] += f.y;
        }
    }
    float* op = out + (size_t)t * HD + c0;
    *(float4*)op       = make_float4(acc[0], acc[1], acc[2], acc[3]);
    *(float4*)(op + 4) = make_float4(acc[4], acc[5], acc[6], acc[7]);
}

// ---------------- launch ----------------
extern "C" void kernel_launch(void* const* d_in, const int* in_sizes, int n_in,
                              void* d_out, int out_size) {
    (void)in_sizes; (void)n_in; (void)out_size;
    const float* x     = (const float*)d_in[0];
    const float* rw    = (const float*)d_in[1];
    const float* gate  = (const float*)d_in[2];
    const float* up    = (const float*)d_in[3];
    const float* down  = (const float*)d_in[4];
    const float* sgate = (const float*)d_in[5];
    const float* sup   = (const float*)d_in[6];
    const float* sdown = (const float*)d_in[7];
    float* out = (float*)d_out;

    cudaFuncSetAttribute(k_gateup, cudaFuncAttributeMaxDynamicSharedMemorySize, GU_SMEM);
    cudaFuncSetAttribute(k_down,   cudaFuncAttributeMaxDynamicSharedMemorySize, DN_SMEM);

    k_init<<<1, 32>>>();
    k_prep<<<NT, 256>>>(x, rw);
    k_gateup<<<dim3(NT / 128, ID / 64, NE), 256, GU_SMEM>>>(gate, up, sgate, sup);
    k_down  <<<dim3(NT / 128, HD / 128, NE), 256, DN_SMEM>>>(down, sdown);
    k_combine<<<NT, 128>>>(out);
}